// round 12
// baseline (speedup 1.0000x reference)
#include <cuda_runtime.h>
#include <cuda_bf16.h>
#include <math.h>
#include <stdint.h>

#define Mq 1024
#define Nn 4096
#define Dd 128
#define Pp 3072
#define Hh 32
#define NKEYS 4096
#define NSPLIT 4
#define KEYB 64
#define NIT ((NKEYS / NSPLIT) / KEYB)   // 16
typedef __nv_bfloat16 bf16;

// ---------------- scratch ----------------
__device__ bf16 g_Xh[(size_t)Mq * Nn],       g_Xl[(size_t)Mq * Nn];
__device__ bf16 g_Qh[(size_t)Hh * Mq * Dd],  g_Ql[(size_t)Hh * Mq * Dd];
__device__ bf16 g_Kh[(size_t)Hh * NKEYS * Dd], g_Kl[(size_t)Hh * NKEYS * Dd];
__device__ bf16 g_Vh[(size_t)Hh * NKEYS * Dd], g_Vl[(size_t)Hh * NKEYS * Dd];
__device__ float g_Opart[(size_t)NSPLIT * Hh * Mq * Dd];
__device__ float g_rs[(size_t)NSPLIT * Hh * Mq];

// ---------------- helpers ----------------
static __device__ __forceinline__ uint32_t smem_u32(const void* p) {
    uint32_t a;
    asm("{ .reg .u64 t; cvta.to.shared.u64 t, %1; cvt.u32.u64 %0, t; }" : "=r"(a) : "l"(p));
    return a;
}
static __device__ __forceinline__ void cp_async16(uint32_t dst, const void* src) {
    asm volatile("cp.async.cg.shared.global [%0], [%1], 16;" :: "r"(dst), "l"(src));
}
#define CP_COMMIT() asm volatile("cp.async.commit_group;" ::: "memory")
#define CP_WAIT(n)  asm volatile("cp.async.wait_group %0;" :: "n"(n) : "memory")

static __device__ __forceinline__ void ldsm_x4(uint32_t& r0, uint32_t& r1, uint32_t& r2, uint32_t& r3,
                                               uint32_t addr) {
    asm volatile("ldmatrix.sync.aligned.m8n8.x4.shared.b16 {%0,%1,%2,%3}, [%4];"
                 : "=r"(r0), "=r"(r1), "=r"(r2), "=r"(r3) : "r"(addr));
}
static __device__ __forceinline__ void ldsm_x4_t(uint32_t& r0, uint32_t& r1, uint32_t& r2, uint32_t& r3,
                                                 uint32_t addr) {
    asm volatile("ldmatrix.sync.aligned.m8n8.x4.trans.shared.b16 {%0,%1,%2,%3}, [%4];"
                 : "=r"(r0), "=r"(r1), "=r"(r2), "=r"(r3) : "r"(addr));
}
static __device__ __forceinline__ void mma_bf16(float* c, const uint32_t* a, const uint32_t* b) {
    asm volatile(
        "mma.sync.aligned.m16n8k16.row.col.f32.bf16.bf16.f32 "
        "{%0,%1,%2,%3}, {%4,%5,%6,%7}, {%8,%9}, {%0,%1,%2,%3};"
        : "+f"(c[0]), "+f"(c[1]), "+f"(c[2]), "+f"(c[3])
        : "r"(a[0]), "r"(a[1]), "r"(a[2]), "r"(a[3]), "r"(b[0]), "r"(b[1]));
}
static __device__ __forceinline__ void split_bf16(float v, bf16& h, bf16& l) {
    h = __float2bfloat16(v);
    l = __float2bfloat16(v - __bfloat162float(h));
}
static __device__ __forceinline__ uint32_t cvt_bf16x2(float a, float b) {
    uint32_t r;
    asm("cvt.rn.bf16x2.f32 %0, %1, %2;" : "=r"(r) : "f"(b), "f"(a));
    return r;
}
static __device__ __forceinline__ void split_pair(float v0, float v1, uint32_t& ph, uint32_t& pl) {
    ph = cvt_bf16x2(v0, v1);
    const float h0 = __uint_as_float(ph << 16);
    const float h1 = __uint_as_float(ph & 0xFFFF0000u);
    pl = cvt_bf16x2(v0 - h0, v1 - h1);
}

// proj smem: rbuf 2048 | X stages 2x64KB | Wf32 stages 2x32KB | Wsplit 32KB = 231424 B
#define PROJ_XS   (2048)
#define PROJ_WF   (2048 + 131072)
#define PROJ_WS   (2048 + 131072 + 65536)
#define SMEM_PROJ (2048 + 131072 + 65536 + 32768)
#define SMEM_ATT  (2048 + 65536 + 65536 + 65536 + 32768)

// ---------------- projection GEMM: TM=256, TN=128, 256 threads, W fp32 streamed ----------------
__global__ __launch_bounds__(256, 1) void proj_kernel(
    const bf16* __restrict__ Xh, const bf16* __restrict__ Xl,
    const float* __restrict__ Wq, const float* __restrict__ Wk, const float* __restrict__ Wv)
{
    extern __shared__ char smem[];
    float* rbuf = (float*)smem;
    const uint32_t sb = smem_u32(smem);
    const int tid = threadIdx.x;
    const int wid = tid >> 5, l = tid & 31;
    const int wm = wid >> 1, wn = wid & 1;
    const int bn = blockIdx.x * 128, bm = blockIdx.y * 256, z = blockIdx.z;

    const float* Wp = (z == 0) ? Wq : (z == 1) ? Wk : Wv;

    float acc[4][8][4];
#pragma unroll
    for (int t = 0; t < 4; t++)
#pragma unroll
        for (int nb = 0; nb < 8; nb++)
#pragma unroll
            for (int i = 0; i < 4; i++) acc[t][nb][i] = 0.f;

    const int nch = Nn >> 6;

    // load X split planes (64KB) + W fp32 rows (32KB, linear [64 rows][512B])
    auto load_chunk = [&](int c) {
        const int k0 = c << 6;
        const uint32_t xb = sb + PROJ_XS + (c & 1) * 65536;
#pragma unroll
        for (int p = 0; p < 2; p++) {
            const bf16* src = p ? Xl : Xh;
#pragma unroll
            for (int i = tid; i < 2048; i += 256) {
                const int row = i >> 3, cc = i & 7;
                const uint32_t off = (uint32_t)(row * 128 + cc * 16);
                cp_async16(xb + p * 32768 + (off ^ (uint32_t)((row & 7) << 4)),
                           src + (size_t)(bm + row) * Nn + k0 + cc * 8);
            }
        }
        const uint32_t wb = sb + PROJ_WF + (c & 1) * 32768;
#pragma unroll
        for (int j = 0; j < 8; j++) {
            const int i = tid + j * 256;          // 0..2047 16B-units
            const int row = i >> 5, c16 = i & 31;
            cp_async16(wb + (uint32_t)(row * 512 + c16 * 16),
                       Wp + (size_t)(k0 + row) * Nn + bn + c16 * 4);
        }
        CP_COMMIT();
    };

    // split Wf32[c&1] -> Wsplit planes (hi @0, lo @16384), layout [64 k][256B] swizzled
    auto split_W = [&](int c) {
        const char* wf = smem + PROJ_WF - 0 + (c & 1) * 32768;   // byte view
        char* ws = smem + PROJ_WS;
#pragma unroll
        for (int j = 0; j < 8; j++) {
            const int i = tid + j * 256;          // 16B-unit index
            const int row = i >> 5, c16 = i & 31;
            const float4 w4 = *(const float4*)(wf + row * 512 + c16 * 16);
            uint32_t h01, l01, h23, l23;
            split_pair(w4.x, w4.y, h01, l01);
            split_pair(w4.z, w4.w, h23, l23);
            const uint32_t off = (uint32_t)(row * 256 + c16 * 8);
            const uint32_t sw = off ^ (uint32_t)((row & 7) << 4);
            *(uint2*)(ws + sw) = make_uint2(h01, h23);
            *(uint2*)(ws + 16384 + sw) = make_uint2(l01, l23);
        }
    };

    load_chunk(0);
    load_chunk(1);

    for (int c = 0; c < nch; c++) {
        if (c + 1 < nch) { CP_WAIT(1); } else { CP_WAIT(0); }
        __syncthreads();                 // cp group c visible; all warps done MMA(c-1)

        split_W(c);
        __syncthreads();                 // Wsplit ready

        const uint32_t xb = sb + PROJ_XS + (c & 1) * 65536;
        const uint32_t wsb = sb + PROJ_WS;
#pragma unroll
        for (int kk = 0; kk < 4; kk++) {
            uint32_t bH[8][2], bL[8][2];
#pragma unroll
            for (int bt = 0; bt < 4; bt++) {
                const int krow = kk * 16 + (l & 7) + ((l >> 3) & 1) * 8;
                const int colb = wn * 128 + bt * 32 + ((l >> 4) & 1) * 16;
                const uint32_t bo = (uint32_t)(krow * 256) + (uint32_t)(colb ^ ((krow & 7) << 4));
                ldsm_x4_t(bH[2 * bt][0], bH[2 * bt][1], bH[2 * bt + 1][0], bH[2 * bt + 1][1],
                          wsb + bo);
                ldsm_x4_t(bL[2 * bt][0], bL[2 * bt][1], bL[2 * bt + 1][0], bL[2 * bt + 1][1],
                          wsb + 16384 + bo);
            }
#pragma unroll
            for (int t = 0; t < 4; t++) {
                uint32_t aH[4], aL[4];
                const int mrow = wm * 64 + t * 16 + (l & 7) + ((l >> 3) & 1) * 8;
                const int kb = kk * 32 + ((l >> 4) & 1) * 16;
                const uint32_t ao = (uint32_t)(mrow * 128) + (uint32_t)(kb ^ ((mrow & 7) << 4));
                ldsm_x4(aH[0], aH[1], aH[2], aH[3], xb + ao);
                ldsm_x4(aL[0], aL[1], aL[2], aL[3], xb + 32768 + ao);
#pragma unroll
                for (int nb = 0; nb < 8; nb++) {
                    mma_bf16(acc[t][nb], aH, bH[nb]);
                    mma_bf16(acc[t][nb], aH, bL[nb]);
                    mma_bf16(acc[t][nb], aL, bH[nb]);
                }
            }
        }
        __syncthreads();                 // done reading X[c&1]/Wf32[c&1]/Wsplit
        if (c + 2 < nch) load_chunk(c + 2);
    }

    if (z < 2) {
        float ss[8];
#pragma unroll
        for (int s = 0; s < 8; s++) ss[s] = 0.f;
#pragma unroll
        for (int t = 0; t < 4; t++)
#pragma unroll
            for (int nb = 0; nb < 8; nb++)
#pragma unroll
                for (int i = 0; i < 4; i++) {
                    const float v = acc[t][nb][i];
                    ss[t * 2 + (i >> 1)] += v * v;
                }
#pragma unroll
        for (int s = 0; s < 8; s++) {
            ss[s] += __shfl_xor_sync(0xffffffffu, ss[s], 1);
            ss[s] += __shfl_xor_sync(0xffffffffu, ss[s], 2);
        }
        if ((l & 3) == 0) {
#pragma unroll
            for (int s = 0; s < 8; s++) {
                const int row = wm * 64 + (s >> 1) * 16 + (l >> 2) + (s & 1) * 8;
                rbuf[wn * 256 + row] = ss[s];
            }
        }
        __syncthreads();
    }

    bf16* dh = (z == 0) ? g_Qh : (z == 1) ? g_Kh : g_Vh;
    bf16* dl = (z == 0) ? g_Ql : (z == 1) ? g_Kl : g_Vl;
#pragma unroll
    for (int t = 0; t < 4; t++)
#pragma unroll
        for (int rh = 0; rh < 2; rh++) {
            const int row = wm * 64 + t * 16 + (l >> 2) + rh * 8;
            float sc = 1.0f;
            if (z < 2) sc = rsqrtf((rbuf[row] + rbuf[256 + row]) * (1.0f / 128.0f));
            const size_t rowbase = (z == 0)
                ? ((size_t)blockIdx.x * Mq + bm + row) * 128
                : ((size_t)blockIdx.x * NKEYS + Pp + bm + row) * 128;
#pragma unroll
            for (int nb = 0; nb < 8; nb++) {
                const int col = wn * 64 + nb * 8 + (l & 3) * 2;
                uint32_t ph, pl;
                split_pair(acc[t][nb][rh * 2 + 0] * sc, acc[t][nb][rh * 2 + 1] * sc, ph, pl);
                *(uint32_t*)(dh + rowbase + col) = ph;
                *(uint32_t*)(dl + rowbase + col) = pl;
            }
        }
}

// ---------------- fused flash attention, split-KV, 64-key iterations (R11, unchanged) ----------------
__global__ __launch_bounds__(512, 1) void attn_kernel()
{
    extern __shared__ char smem[];
    float* rbuf = (float*)smem;
    const uint32_t sb = smem_u32(smem);
    const uint32_t Qb = sb + 2048;
    const uint32_t Kr = Qb + 65536;
    const uint32_t Vr = Kr + 65536;
    const uint32_t Pb = Vr + 65536;

    const int tid = threadIdx.x;
    const int wid = tid >> 5, l = tid & 31;
    const int wm = wid >> 2, wn = wid & 3;
    const int bm = blockIdx.x * 128;
    const int z = blockIdx.y;
    const int sp = blockIdx.z;
    const int key0 = sp * (NKEYS / NSPLIT);

    const bf16* Qhp = g_Qh + ((size_t)z * Mq + bm) * Dd;
    const bf16* Qlp = g_Ql + ((size_t)z * Mq + bm) * Dd;
    const bf16* Khp = g_Kh + (size_t)z * NKEYS * Dd;
    const bf16* Klp = g_Kl + (size_t)z * NKEYS * Dd;
    const bf16* Vhp = g_Vh + (size_t)z * NKEYS * Dd;
    const bf16* Vlp = g_Vl + (size_t)z * NKEYS * Dd;

    auto load_Q = [&]() {
#pragma unroll
        for (int j = 0; j < 8; j++) {
            const int i = tid + j * 512;
            const int plane = i >> 10, row = (i >> 3) & 127, cc = i & 7;
            const bf16* src = (plane < 2) ? Qhp : Qlp;
            const int k0 = (plane & 1) * 64;
            const uint32_t off = (uint32_t)(row * 128 + cc * 16);
            cp_async16(Qb + plane * 16384 + (off ^ (uint32_t)((row & 7) << 4)),
                       src + (size_t)row * Dd + k0 + cc * 8);
        }
    };
    auto load_K = [&](int buf, int krow0) {
#pragma unroll
        for (int j = 0; j < 4; j++) {
            const int i = tid + j * 512;
            const int plane = i >> 9, row = (i >> 3) & 63, cc = i & 7;
            const bf16* src = (plane < 2) ? Khp : Klp;
            const int k0 = (plane & 1) * 64;
            const uint32_t off = (uint32_t)(row * 128 + cc * 16);
            cp_async16(Kr + buf * 32768 + plane * 8192 + (off ^ (uint32_t)((row & 7) << 4)),
                       src + (size_t)(krow0 + row) * Dd + k0 + cc * 8);
        }
    };
    auto load_V = [&](int buf, int krow0) {
#pragma unroll
        for (int j = 0; j < 4; j++) {
            const int i = tid + j * 512;
            const int plane = i >> 10, row = (i >> 4) & 63, c16 = i & 15;
            const bf16* src = plane ? Vlp : Vhp;
            const uint32_t off = (uint32_t)(row * 256 + c16 * 16);
            cp_async16(Vr + buf * 32768 + plane * 16384 + (off ^ (uint32_t)((row & 7) << 4)),
                       src + (size_t)(krow0 + row) * Dd + c16 * 8);
        }
    };

    auto do_mma_qk = [&](float acc[2][2][4], uint32_t kbuf) {
#pragma unroll
        for (int c = 0; c < 2; c++) {
            const uint32_t aHb = Qb + c * 16384, aLb = Qb + 32768 + c * 16384;
            const uint32_t bHb = kbuf + c * 8192, bLb = kbuf + 16384 + c * 8192;
#pragma unroll
            for (int kk = 0; kk < 4; kk++) {
                uint32_t aH[2][4], aL[2][4];
#pragma unroll
                for (int t = 0; t < 2; t++) {
                    const int mrow = wm * 32 + t * 16 + (l & 7) + ((l >> 3) & 1) * 8;
                    const int kb = kk * 32 + ((l >> 4) & 1) * 16;
                    const uint32_t ao = (uint32_t)(mrow * 128) + (uint32_t)(kb ^ ((mrow & 7) << 4));
                    ldsm_x4(aH[t][0], aH[t][1], aH[t][2], aH[t][3], aHb + ao);
                    ldsm_x4(aL[t][0], aL[t][1], aL[t][2], aL[t][3], aLb + ao);
                }
                uint32_t bH[2][2], bL[2][2];
                {
                    const int nrow = wn * 16 + (l & 7) + ((l >> 4) & 1) * 8;
                    const int kb = kk * 32 + ((l >> 3) & 1) * 16;
                    const uint32_t bo = (uint32_t)(nrow * 128) + (uint32_t)(kb ^ ((nrow & 7) << 4));
                    ldsm_x4(bH[0][0], bH[0][1], bH[1][0], bH[1][1], bHb + bo);
                    ldsm_x4(bL[0][0], bL[0][1], bL[1][0], bL[1][1], bLb + bo);
                }
#pragma unroll
                for (int t = 0; t < 2; t++)
#pragma unroll
                    for (int nb = 0; nb < 2; nb++) {
                        mma_bf16(acc[t][nb], aH[t], bH[nb]);
                        mma_bf16(acc[t][nb], aH[t], bL[nb]);
                        mma_bf16(acc[t][nb], aL[t], bH[nb]);
                    }
            }
        }
    };

    auto do_mma_pv = [&](float acc[2][4][4], uint32_t vbuf) {
#pragma unroll
        for (int kk = 0; kk < 4; kk++) {
            uint32_t aH[2][4], aL[2][4];
#pragma unroll
            for (int t = 0; t < 2; t++) {
                const int mrow = wm * 32 + t * 16 + (l & 7) + ((l >> 3) & 1) * 8;
                const int kb = kk * 32 + ((l >> 4) & 1) * 16;
                const uint32_t ao = (uint32_t)(mrow * 128) + (uint32_t)(kb ^ ((mrow & 7) << 4));
                ldsm_x4(aH[t][0], aH[t][1], aH[t][2], aH[t][3], Pb + ao);
                ldsm_x4(aL[t][0], aL[t][1], aL[t][2], aL[t][3], Pb + 16384 + ao);
            }
            uint32_t bH[4][2], bL[4][2];
#pragma unroll
            for (int bt = 0; bt < 2; bt++) {
                const int key = kk * 16 + (l & 7) + ((l >> 3) & 1) * 8;
                const int colb = wn * 64 + bt * 32 + ((l >> 4) & 1) * 16;
                const uint32_t bo = (uint32_t)(key * 256) + (uint32_t)(colb ^ ((key & 7) << 4));
                ldsm_x4_t(bH[2 * bt][0], bH[2 * bt][1], bH[2 * bt + 1][0], bH[2 * bt + 1][1],
                          vbuf + bo);
                ldsm_x4_t(bL[2 * bt][0], bL[2 * bt][1], bL[2 * bt + 1][0], bL[2 * bt + 1][1],
                          vbuf + 16384 + bo);
            }
#pragma unroll
            for (int t = 0; t < 2; t++)
#pragma unroll
                for (int nb = 0; nb < 4; nb++) {
                    mma_bf16(acc[t][nb], aH[t], bH[nb]);
                    mma_bf16(acc[t][nb], aH[t], bL[nb]);
                    mma_bf16(acc[t][nb], aL[t], bH[nb]);
                }
        }
    };

    float accO[2][4][4];
#pragma unroll
    for (int t = 0; t < 2; t++)
#pragma unroll
        for (int nb = 0; nb < 4; nb++)
#pragma unroll
            for (int i = 0; i < 4; i++) accO[t][nb][i] = 0.f;
    float rs[4] = {0.f, 0.f, 0.f, 0.f};

    load_Q();
    load_K(0, key0);
    load_V(0, key0);
    CP_COMMIT();

    for (int it = 0; it < NIT; it++) {
        CP_WAIT(0);
        __syncthreads();

        if (it + 1 < NIT) {
            load_K((it + 1) & 1, key0 + (it + 1) * KEYB);
            load_V((it + 1) & 1, key0 + (it + 1) * KEYB);
        }
        CP_COMMIT();

        float accS[2][2][4];
#pragma unroll
        for (int t = 0; t < 2; t++)
#pragma unroll
            for (int nb = 0; nb < 2; nb++)
#pragma unroll
                for (int i = 0; i < 4; i++) accS[t][nb][i] = 0.f;

        do_mma_qk(accS, Kr + (it & 1) * 32768);

#pragma unroll
        for (int t = 0; t < 2; t++)
#pragma unroll
            for (int rh = 0; rh < 2; rh++) {
                const int row = wm * 32 + t * 16 + (l >> 2) + rh * 8;
#pragma unroll
                for (int nb = 0; nb < 2; nb++) {
                    const int col = wn * 16 + nb * 8 + (l & 3) * 2;
                    const float e0 = __expf(accS[t][nb][rh * 2 + 0]);
                    const float e1 = __expf(accS[t][nb][rh * 2 + 1]);
                    rs[t * 2 + rh] += e0 + e1;
                    uint32_t ph, pl;
                    split_pair(e0, e1, ph, pl);
                    const uint32_t off = (uint32_t)(row * 128 + col * 2);
                    const uint32_t sw = off ^ (uint32_t)((row & 7) << 4);
                    *(uint32_t*)(smem + (Pb - sb) + sw) = ph;
                    *(uint32_t*)(smem + (Pb - sb) + 16384 + sw) = pl;
                }
            }
        __syncthreads();

        do_mma_pv(accO, Vr + (it & 1) * 32768);
    }

#pragma unroll
    for (int s = 0; s < 4; s++) {
        rs[s] += __shfl_xor_sync(0xffffffffu, rs[s], 1);
        rs[s] += __shfl_xor_sync(0xffffffffu, rs[s], 2);
    }
    __syncthreads();
    if ((l & 3) == 0) {
#pragma unroll
        for (int s = 0; s < 4; s++) {
            const int row = wm * 32 + (s >> 1) * 16 + (l >> 2) + (s & 1) * 8;
            rbuf[wn * 128 + row] = rs[s];
        }
    }
    __syncthreads();

    if (tid < 128) {
        g_rs[((size_t)sp * Hh + z) * Mq + bm + tid] =
            rbuf[tid] + rbuf[128 + tid] + rbuf[256 + tid] + rbuf[384 + tid];
    }

    float* obase = g_Opart + (((size_t)sp * Hh + z) * Mq + bm) * Dd;
#pragma unroll
    for (int t = 0; t < 2; t++)
#pragma unroll
        for (int rh = 0; rh < 2; rh++) {
            const int row = wm * 32 + t * 16 + (l >> 2) + rh * 8;
#pragma unroll
            for (int nb = 0; nb < 4; nb++) {
                const int col = wn * 32 + nb * 8 + (l & 3) * 2;
                float2 v;
                v.x = accO[t][nb][rh * 2 + 0];
                v.y = accO[t][nb][rh * 2 + 1];
                *(float2*)(obase + (size_t)row * Dd + col) = v;
            }
        }
}

// ---------------- combine partials -> out ----------------
__global__ __launch_bounds__(256) void combine_kernel(float* __restrict__ outp)
{
    const size_t idx = (size_t)blockIdx.x * blockDim.x + threadIdx.x;
    const size_t e = idx * 4;
    const int m = (int)(e >> 12);
    const int c = (int)(e & (Nn - 1));
    const int h = c >> 7;
    const int d = c & 127;

    const size_t rbase = (size_t)h * Mq + m;
    const float tot = g_rs[rbase] + g_rs[(size_t)Hh * Mq + rbase]
                    + g_rs[2 * (size_t)Hh * Mq + rbase] + g_rs[3 * (size_t)Hh * Mq + rbase];
    const float inv = 1.0f / tot;

    const size_t pbase = ((size_t)h * Mq + m) * Dd + d;
    const size_t pstep = (size_t)Hh * Mq * Dd;
    float4 a = *(const float4*)(g_Opart + pbase);
    float4 b = *(const float4*)(g_Opart + pbase + pstep);
    float4 cc = *(const float4*)(g_Opart + pbase + 2 * pstep);
    float4 dd = *(const float4*)(g_Opart + pbase + 3 * pstep);
    float4 o;
    o.x = (a.x + b.x + cc.x + dd.x) * inv;
    o.y = (a.y + b.y + cc.y + dd.y) * inv;
    o.z = (a.z + b.z + cc.z + dd.z) * inv;
    o.w = (a.w + b.w + cc.w + dd.w) * inv;
    *(float4*)(outp + e) = o;
}

// ---------------- prep ----------------
__global__ __launch_bounds__(256) void convert_inputs(
    const float* __restrict__ X, const float* __restrict__ cK, const float* __restrict__ cV)
{
    const size_t stride = (size_t)gridDim.x * blockDim.x;
    const size_t tid0 = (size_t)blockIdx.x * blockDim.x + threadIdx.x;

    for (size_t i = tid0; i < (size_t)Mq * Nn; i += stride) {
        bf16 h, lo;
        split_bf16(X[i], h, lo);
        g_Xh[i] = h; g_Xl[i] = lo;
    }
    const size_t nkv = (size_t)Hh * Pp * Dd;
    for (size_t i = tid0; i < nkv; i += stride) {
        const size_t h = i / ((size_t)Pp * Dd);
        const size_t r = i % ((size_t)Pp * Dd);
        const size_t o = h * (size_t)NKEYS * Dd + r;
        bf16 hh, lo;
        split_bf16(cK[i], hh, lo);
        g_Kh[o] = hh; g_Kl[o] = lo;
        split_bf16(cV[i], hh, lo);
        g_Vh[o] = hh; g_Vl[o] = lo;
    }
}

// ---------------- host launcher ----------------
extern "C" void kernel_launch(void* const* d_in, const int* in_sizes, int n_in,
                              void* d_out, int out_size)
{
    const float* X  = (const float*)d_in[0];
    const float* Wq = (const float*)d_in[1];
    const float* Wk = (const float*)d_in[2];
    const float* Wv = (const float*)d_in[3];
    const float* cK = (const float*)d_in[4];
    const float* cV = (const float*)d_in[5];
    float* out = (float*)d_out;

    bf16 *xh, *xl;
    cudaGetSymbolAddress((void**)&xh, g_Xh);
    cudaGetSymbolAddress((void**)&xl, g_Xl);

    cudaFuncSetAttribute(proj_kernel, cudaFuncAttributeMaxDynamicSharedMemorySize, SMEM_PROJ);
    cudaFuncSetAttribute(attn_kernel, cudaFuncAttributeMaxDynamicSharedMemorySize, SMEM_ATT);

    convert_inputs<<<4096, 256>>>(X, cK, cV);

    proj_kernel<<<dim3(Nn / 128, Mq / 256, 3), 256, SMEM_PROJ>>>(xh, xl, Wq, Wk, Wv);

    attn_kernel<<<dim3(Mq / 128, Hh, NSPLIT), 512, SMEM_ATT>>>();

    combine_kernel<<<(Mq * Nn / 4) / 256, 256>>>(out);
}

// round 13
// speedup vs baseline: 1.0080x; 1.0080x over previous
#include <cuda_runtime.h>
#include <cuda_bf16.h>
#include <math.h>
#include <stdint.h>

#define Mq 1024
#define Nn 4096
#define Dd 128
#define Pp 3072
#define Hh 32
#define NKEYS 4096
#define NSPLIT 4
#define KEYB 64
#define NIT ((NKEYS / NSPLIT) / KEYB)   // 16
typedef __nv_bfloat16 bf16;

// ---------------- scratch ----------------
__device__ bf16 g_Xh[(size_t)Mq * Nn],       g_Xl[(size_t)Mq * Nn];
__device__ bf16 g_Qh[(size_t)Hh * Mq * Dd],  g_Ql[(size_t)Hh * Mq * Dd];
__device__ bf16 g_Kh[(size_t)Hh * NKEYS * Dd], g_Kl[(size_t)Hh * NKEYS * Dd];
__device__ bf16 g_Vh[(size_t)Hh * NKEYS * Dd], g_Vl[(size_t)Hh * NKEYS * Dd];
__device__ float g_Opart[(size_t)NSPLIT * Hh * Mq * Dd];
__device__ float g_rs[(size_t)NSPLIT * Hh * Mq];

// ---------------- helpers ----------------
static __device__ __forceinline__ uint32_t smem_u32(const void* p) {
    uint32_t a;
    asm("{ .reg .u64 t; cvta.to.shared.u64 t, %1; cvt.u32.u64 %0, t; }" : "=r"(a) : "l"(p));
    return a;
}
static __device__ __forceinline__ void cp_async16(uint32_t dst, const void* src) {
    asm volatile("cp.async.cg.shared.global [%0], [%1], 16;" :: "r"(dst), "l"(src));
}
#define CP_COMMIT() asm volatile("cp.async.commit_group;" ::: "memory")
#define CP_WAIT(n)  asm volatile("cp.async.wait_group %0;" :: "n"(n) : "memory")

static __device__ __forceinline__ void ldsm_x4(uint32_t& r0, uint32_t& r1, uint32_t& r2, uint32_t& r3,
                                               uint32_t addr) {
    asm volatile("ldmatrix.sync.aligned.m8n8.x4.shared.b16 {%0,%1,%2,%3}, [%4];"
                 : "=r"(r0), "=r"(r1), "=r"(r2), "=r"(r3) : "r"(addr));
}
static __device__ __forceinline__ void ldsm_x4_t(uint32_t& r0, uint32_t& r1, uint32_t& r2, uint32_t& r3,
                                                 uint32_t addr) {
    asm volatile("ldmatrix.sync.aligned.m8n8.x4.trans.shared.b16 {%0,%1,%2,%3}, [%4];"
                 : "=r"(r0), "=r"(r1), "=r"(r2), "=r"(r3) : "r"(addr));
}
static __device__ __forceinline__ void mma_bf16(float* c, const uint32_t* a, const uint32_t* b) {
    asm volatile(
        "mma.sync.aligned.m16n8k16.row.col.f32.bf16.bf16.f32 "
        "{%0,%1,%2,%3}, {%4,%5,%6,%7}, {%8,%9}, {%0,%1,%2,%3};"
        : "+f"(c[0]), "+f"(c[1]), "+f"(c[2]), "+f"(c[3])
        : "r"(a[0]), "r"(a[1]), "r"(a[2]), "r"(a[3]), "r"(b[0]), "r"(b[1]));
}
static __device__ __forceinline__ void split_bf16(float v, bf16& h, bf16& l) {
    h = __float2bfloat16(v);
    l = __float2bfloat16(v - __bfloat162float(h));
}
static __device__ __forceinline__ uint32_t cvt_bf16x2(float a, float b) {
    uint32_t r;
    asm("cvt.rn.bf16x2.f32 %0, %1, %2;" : "=r"(r) : "f"(b), "f"(a));
    return r;
}
static __device__ __forceinline__ void split_pair(float v0, float v1, uint32_t& ph, uint32_t& pl) {
    ph = cvt_bf16x2(v0, v1);
    const float h0 = __uint_as_float(ph << 16);
    const float h1 = __uint_as_float(ph & 0xFFFF0000u);
    pl = cvt_bf16x2(v0 - h0, v1 - h1);
}

// proj smem: rbuf 2048 | X stages 2x64KB | Wf32 stages 2x32KB | Wsplit 32KB
#define PROJ_XS   (2048)
#define PROJ_WF   (2048 + 131072)
#define PROJ_WS   (2048 + 131072 + 65536)
#define SMEM_PROJ (2048 + 131072 + 65536 + 32768)
// attn: rbuf 2048 | Q 64K (reused as O-reduce buf) | K ring 2x32K | V ring 2x32K
#define SMEM_ATT  (2048 + 65536 + 65536 + 65536)

// ---------------- projection GEMM (R12, unchanged) ----------------
__global__ __launch_bounds__(256, 1) void proj_kernel(
    const bf16* __restrict__ Xh, const bf16* __restrict__ Xl,
    const float* __restrict__ Wq, const float* __restrict__ Wk, const float* __restrict__ Wv)
{
    extern __shared__ char smem[];
    float* rbuf = (float*)smem;
    const uint32_t sb = smem_u32(smem);
    const int tid = threadIdx.x;
    const int wid = tid >> 5, l = tid & 31;
    const int wm = wid >> 1, wn = wid & 1;
    const int bn = blockIdx.x * 128, bm = blockIdx.y * 256, z = blockIdx.z;

    const float* Wp = (z == 0) ? Wq : (z == 1) ? Wk : Wv;

    float acc[4][8][4];
#pragma unroll
    for (int t = 0; t < 4; t++)
#pragma unroll
        for (int nb = 0; nb < 8; nb++)
#pragma unroll
            for (int i = 0; i < 4; i++) acc[t][nb][i] = 0.f;

    const int nch = Nn >> 6;

    auto load_chunk = [&](int c) {
        const int k0 = c << 6;
        const uint32_t xb = sb + PROJ_XS + (c & 1) * 65536;
#pragma unroll
        for (int p = 0; p < 2; p++) {
            const bf16* src = p ? Xl : Xh;
#pragma unroll
            for (int i = tid; i < 2048; i += 256) {
                const int row = i >> 3, cc = i & 7;
                const uint32_t off = (uint32_t)(row * 128 + cc * 16);
                cp_async16(xb + p * 32768 + (off ^ (uint32_t)((row & 7) << 4)),
                           src + (size_t)(bm + row) * Nn + k0 + cc * 8);
            }
        }
        const uint32_t wb = sb + PROJ_WF + (c & 1) * 32768;
#pragma unroll
        for (int j = 0; j < 8; j++) {
            const int i = tid + j * 256;
            const int row = i >> 5, c16 = i & 31;
            cp_async16(wb + (uint32_t)(row * 512 + c16 * 16),
                       Wp + (size_t)(k0 + row) * Nn + bn + c16 * 4);
        }
        CP_COMMIT();
    };

    auto split_W = [&](int c) {
        const char* wf = smem + PROJ_WF + (c & 1) * 32768;
        char* ws = smem + PROJ_WS;
#pragma unroll
        for (int j = 0; j < 8; j++) {
            const int i = tid + j * 256;
            const int row = i >> 5, c16 = i & 31;
            const float4 w4 = *(const float4*)(wf + row * 512 + c16 * 16);
            uint32_t h01, l01, h23, l23;
            split_pair(w4.x, w4.y, h01, l01);
            split_pair(w4.z, w4.w, h23, l23);
            const uint32_t off = (uint32_t)(row * 256 + c16 * 8);
            const uint32_t sw = off ^ (uint32_t)((row & 7) << 4);
            *(uint2*)(ws + sw) = make_uint2(h01, h23);
            *(uint2*)(ws + 16384 + sw) = make_uint2(l01, l23);
        }
    };

    load_chunk(0);
    load_chunk(1);

    for (int c = 0; c < nch; c++) {
        if (c + 1 < nch) { CP_WAIT(1); } else { CP_WAIT(0); }
        __syncthreads();

        split_W(c);
        __syncthreads();

        const uint32_t xb = sb + PROJ_XS + (c & 1) * 65536;
        const uint32_t wsb = sb + PROJ_WS;
#pragma unroll
        for (int kk = 0; kk < 4; kk++) {
            uint32_t bH[8][2], bL[8][2];
#pragma unroll
            for (int bt = 0; bt < 4; bt++) {
                const int krow = kk * 16 + (l & 7) + ((l >> 3) & 1) * 8;
                const int colb = wn * 128 + bt * 32 + ((l >> 4) & 1) * 16;
                const uint32_t bo = (uint32_t)(krow * 256) + (uint32_t)(colb ^ ((krow & 7) << 4));
                ldsm_x4_t(bH[2 * bt][0], bH[2 * bt][1], bH[2 * bt + 1][0], bH[2 * bt + 1][1],
                          wsb + bo);
                ldsm_x4_t(bL[2 * bt][0], bL[2 * bt][1], bL[2 * bt + 1][0], bL[2 * bt + 1][1],
                          wsb + 16384 + bo);
            }
#pragma unroll
            for (int t = 0; t < 4; t++) {
                uint32_t aH[4], aL[4];
                const int mrow = wm * 64 + t * 16 + (l & 7) + ((l >> 3) & 1) * 8;
                const int kb = kk * 32 + ((l >> 4) & 1) * 16;
                const uint32_t ao = (uint32_t)(mrow * 128) + (uint32_t)(kb ^ ((mrow & 7) << 4));
                ldsm_x4(aH[0], aH[1], aH[2], aH[3], xb + ao);
                ldsm_x4(aL[0], aL[1], aL[2], aL[3], xb + 32768 + ao);
#pragma unroll
                for (int nb = 0; nb < 8; nb++) {
                    mma_bf16(acc[t][nb], aH, bH[nb]);
                    mma_bf16(acc[t][nb], aH, bL[nb]);
                    mma_bf16(acc[t][nb], aL, bH[nb]);
                }
            }
        }
        __syncthreads();
        if (c + 2 < nch) load_chunk(c + 2);
    }

    if (z < 2) {
        float ss[8];
#pragma unroll
        for (int s = 0; s < 8; s++) ss[s] = 0.f;
#pragma unroll
        for (int t = 0; t < 4; t++)
#pragma unroll
            for (int nb = 0; nb < 8; nb++)
#pragma unroll
                for (int i = 0; i < 4; i++) {
                    const float v = acc[t][nb][i];
                    ss[t * 2 + (i >> 1)] += v * v;
                }
#pragma unroll
        for (int s = 0; s < 8; s++) {
            ss[s] += __shfl_xor_sync(0xffffffffu, ss[s], 1);
            ss[s] += __shfl_xor_sync(0xffffffffu, ss[s], 2);
        }
        if ((l & 3) == 0) {
#pragma unroll
            for (int s = 0; s < 8; s++) {
                const int row = wm * 64 + (s >> 1) * 16 + (l >> 2) + (s & 1) * 8;
                rbuf[wn * 256 + row] = ss[s];
            }
        }
        __syncthreads();
    }

    bf16* dh = (z == 0) ? g_Qh : (z == 1) ? g_Kh : g_Vh;
    bf16* dl = (z == 0) ? g_Ql : (z == 1) ? g_Kl : g_Vl;
#pragma unroll
    for (int t = 0; t < 4; t++)
#pragma unroll
        for (int rh = 0; rh < 2; rh++) {
            const int row = wm * 64 + t * 16 + (l >> 2) + rh * 8;
            float sc = 1.0f;
            if (z < 2) sc = rsqrtf((rbuf[row] + rbuf[256 + row]) * (1.0f / 128.0f));
            const size_t rowbase = (z == 0)
                ? ((size_t)blockIdx.x * Mq + bm + row) * 128
                : ((size_t)blockIdx.x * NKEYS + Pp + bm + row) * 128;
#pragma unroll
            for (int nb = 0; nb < 8; nb++) {
                const int col = wn * 64 + nb * 8 + (l & 3) * 2;
                uint32_t ph, pl;
                split_pair(acc[t][nb][rh * 2 + 0] * sc, acc[t][nb][rh * 2 + 1] * sc, ph, pl);
                *(uint32_t*)(dh + rowbase + col) = ph;
                *(uint32_t*)(dl + rowbase + col) = pl;
            }
        }
}

// ---------------- fused flash attention: register-resident P, 256 threads ----------------
// 8 warps: wm (0..3) x wn (0..1). Each warp: rows wm*32..+31, keys wn*32..+31 per iter,
// PV partial over its keys across full 128 d-cols; cross-wn add at the end.
__global__ __launch_bounds__(256, 1) void attn_kernel()
{
    extern __shared__ char smem[];
    float* rbuf = (float*)smem;
    const uint32_t sb = smem_u32(smem);
    const uint32_t Qb = sb + 2048;            // also O-reduce buffer at the end
    const uint32_t Kr = Qb + 65536;           // 2 x 32KB
    const uint32_t Vr = Kr + 65536;           // 2 x 32KB

    const int tid = threadIdx.x;
    const int wid = tid >> 5, l = tid & 31;
    const int wm = wid >> 1, wn = wid & 1;
    const int bm = blockIdx.x * 128;
    const int z = blockIdx.y;
    const int sp = blockIdx.z;
    const int key0 = sp * (NKEYS / NSPLIT);

    const bf16* Qhp = g_Qh + ((size_t)z * Mq + bm) * Dd;
    const bf16* Qlp = g_Ql + ((size_t)z * Mq + bm) * Dd;
    const bf16* Khp = g_Kh + (size_t)z * NKEYS * Dd;
    const bf16* Klp = g_Kl + (size_t)z * NKEYS * Dd;
    const bf16* Vhp = g_Vh + (size_t)z * NKEYS * Dd;
    const bf16* Vlp = g_Vl + (size_t)z * NKEYS * Dd;

    auto load_Q = [&]() {
#pragma unroll
        for (int j = 0; j < 16; j++) {
            const int i = tid + j * 256;
            const int plane = i >> 10, row = (i >> 3) & 127, cc = i & 7;
            const bf16* src = (plane < 2) ? Qhp : Qlp;
            const int k0 = (plane & 1) * 64;
            const uint32_t off = (uint32_t)(row * 128 + cc * 16);
            cp_async16(Qb + plane * 16384 + (off ^ (uint32_t)((row & 7) << 4)),
                       src + (size_t)row * Dd + k0 + cc * 8);
        }
    };
    auto load_K = [&](int buf, int krow0) {
#pragma unroll
        for (int j = 0; j < 8; j++) {
            const int i = tid + j * 256;
            const int plane = i >> 9, row = (i >> 3) & 63, cc = i & 7;
            const bf16* src = (plane < 2) ? Khp : Klp;
            const int k0 = (plane & 1) * 64;
            const uint32_t off = (uint32_t)(row * 128 + cc * 16);
            cp_async16(Kr + buf * 32768 + plane * 8192 + (off ^ (uint32_t)((row & 7) << 4)),
                       src + (size_t)(krow0 + row) * Dd + k0 + cc * 8);
        }
    };
    auto load_V = [&](int buf, int krow0) {
#pragma unroll
        for (int j = 0; j < 8; j++) {
            const int i = tid + j * 256;
            const int plane = i >> 10, row = (i >> 4) & 63, c16 = i & 15;
            const bf16* src = plane ? Vlp : Vhp;
            const uint32_t off = (uint32_t)(row * 256 + c16 * 16);
            cp_async16(Vr + buf * 32768 + plane * 16384 + (off ^ (uint32_t)((row & 7) << 4)),
                       src + (size_t)(krow0 + row) * Dd + c16 * 8);
        }
    };

    // QK: A = Q (rows wm*32..+31), B = K keys wn*32..+31 -> accS[2][4][4]
    auto do_mma_qk = [&](float acc[2][4][4], uint32_t kbuf) {
#pragma unroll
        for (int c = 0; c < 2; c++) {
            const uint32_t aHb = Qb + c * 16384, aLb = Qb + 32768 + c * 16384;
            const uint32_t bHb = kbuf + c * 8192, bLb = kbuf + 16384 + c * 8192;
#pragma unroll
            for (int kk = 0; kk < 4; kk++) {
                uint32_t aH[2][4], aL[2][4];
#pragma unroll
                for (int t = 0; t < 2; t++) {
                    const int mrow = wm * 32 + t * 16 + (l & 7) + ((l >> 3) & 1) * 8;
                    const int kb = kk * 32 + ((l >> 4) & 1) * 16;
                    const uint32_t ao = (uint32_t)(mrow * 128) + (uint32_t)(kb ^ ((mrow & 7) << 4));
                    ldsm_x4(aH[t][0], aH[t][1], aH[t][2], aH[t][3], aHb + ao);
                    ldsm_x4(aL[t][0], aL[t][1], aL[t][2], aL[t][3], aLb + ao);
                }
                uint32_t bH[4][2], bL[4][2];
#pragma unroll
                for (int bt = 0; bt < 2; bt++) {
                    const int nrow = wn * 32 + bt * 16 + (l & 7) + ((l >> 4) & 1) * 8;
                    const int kb = kk * 32 + ((l >> 3) & 1) * 16;
                    const uint32_t bo = (uint32_t)(nrow * 128) + (uint32_t)(kb ^ ((nrow & 7) << 4));
                    ldsm_x4(bH[2 * bt][0], bH[2 * bt][1], bH[2 * bt + 1][0], bH[2 * bt + 1][1], bHb + bo);
                    ldsm_x4(bL[2 * bt][0], bL[2 * bt][1], bL[2 * bt + 1][0], bL[2 * bt + 1][1], bLb + bo);
                }
#pragma unroll
                for (int t = 0; t < 2; t++)
#pragma unroll
                    for (int nb = 0; nb < 4; nb++) {
                        mma_bf16(acc[t][nb], aH[t], bH[nb]);
                        mma_bf16(acc[t][nb], aH[t], bL[nb]);
                        mma_bf16(acc[t][nb], aL[t], bH[nb]);
                    }
            }
        }
    };

    float accO[2][16][4];
#pragma unroll
    for (int t = 0; t < 2; t++)
#pragma unroll
        for (int nb = 0; nb < 16; nb++)
#pragma unroll
            for (int i = 0; i < 4; i++) accO[t][nb][i] = 0.f;
    float rs[4] = {0.f, 0.f, 0.f, 0.f};

    load_Q();
    load_K(0, key0);
    load_V(0, key0);
    CP_COMMIT();

    for (int it = 0; it < NIT; it++) {
        CP_WAIT(0);
        __syncthreads();

        if (it + 1 < NIT) {
            load_K((it + 1) & 1, key0 + (it + 1) * KEYB);
            load_V((it + 1) & 1, key0 + (it + 1) * KEYB);
        }
        CP_COMMIT();

        float accS[2][4][4];
#pragma unroll
        for (int t = 0; t < 2; t++)
#pragma unroll
            for (int nb = 0; nb < 4; nb++)
#pragma unroll
                for (int i = 0; i < 4; i++) accS[t][nb][i] = 0.f;

        do_mma_qk(accS, Kr + (it & 1) * 32768);

        // exp + split into PV A-fragments, all in registers
        uint32_t pH[2][4][2], pL[2][4][2];
#pragma unroll
        for (int t = 0; t < 2; t++)
#pragma unroll
            for (int nb = 0; nb < 4; nb++)
#pragma unroll
                for (int rh = 0; rh < 2; rh++) {
                    const float e0 = __expf(accS[t][nb][rh * 2 + 0]);
                    const float e1 = __expf(accS[t][nb][rh * 2 + 1]);
                    rs[t * 2 + rh] += e0 + e1;
                    split_pair(e0, e1, pH[t][nb][rh], pL[t][nb][rh]);
                }

        // PV: contraction over this warp's 32 keys (2 k16 steps), full 128 d-cols
        const uint32_t vbuf = Vr + (it & 1) * 32768;
#pragma unroll
        for (int st = 0; st < 2; st++) {
            uint32_t aH[2][4], aL[2][4];
#pragma unroll
            for (int t = 0; t < 2; t++) {
                aH[t][0] = pH[t][2 * st][0];
                aH[t][1] = pH[t][2 * st][1];
                aH[t][2] = pH[t][2 * st + 1][0];
                aH[t][3] = pH[t][2 * st + 1][1];
                aL[t][0] = pL[t][2 * st][0];
                aL[t][1] = pL[t][2 * st][1];
                aL[t][2] = pL[t][2 * st + 1][0];
                aL[t][3] = pL[t][2 * st + 1][1];
            }
            const int key = (wn * 2 + st) * 16 + (l & 7) + ((l >> 3) & 1) * 8;
#pragma unroll
            for (int bt = 0; bt < 8; bt++) {
                const int colb = bt * 32 + ((l >> 4) & 1) * 16;
                const uint32_t bo = (uint32_t)(key * 256) + (uint32_t)(colb ^ ((key & 7) << 4));
                uint32_t bH[2][2], bL[2][2];
                ldsm_x4_t(bH[0][0], bH[0][1], bH[1][0], bH[1][1], vbuf + bo);
                ldsm_x4_t(bL[0][0], bL[0][1], bL[1][0], bL[1][1], vbuf + 16384 + bo);
#pragma unroll
                for (int t = 0; t < 2; t++)
#pragma unroll
                    for (int j = 0; j < 2; j++) {
                        mma_bf16(accO[t][2 * bt + j], aH[t], bH[j]);
                        mma_bf16(accO[t][2 * bt + j], aH[t], bL[j]);
                        mma_bf16(accO[t][2 * bt + j], aL[t], bH[j]);
                    }
            }
        }
        __syncthreads();   // all warps done with K/V buffers of this iter
    }

    // ---- cross-wn accO reduction via smem (reuse Q region) + rs reduction ----
    float* obuf = (float*)(smem + 2048);   // 128 x 128 fp32 = 64KB

    if (wn == 1) {
#pragma unroll
        for (int t = 0; t < 2; t++)
#pragma unroll
            for (int rh = 0; rh < 2; rh++) {
                const int row = wm * 32 + t * 16 + (l >> 2) + rh * 8;
#pragma unroll
                for (int nb = 0; nb < 16; nb++) {
                    const int col = nb * 8 + (l & 3) * 2;
                    float2 v;
                    v.x = accO[t][nb][rh * 2 + 0];
                    v.y = accO[t][nb][rh * 2 + 1];
                    *(float2*)(obuf + row * 128 + col) = v;
                }
            }
    }

    // rs quad reduce (cols within a quad share nothing; sum pairs)
#pragma unroll
    for (int s = 0; s < 4; s++) {
        rs[s] += __shfl_xor_sync(0xffffffffu, rs[s], 1);
        rs[s] += __shfl_xor_sync(0xffffffffu, rs[s], 2);
    }
    __syncthreads();       // obuf ready

    if ((l & 3) == 0) {
#pragma unroll
        for (int s = 0; s < 4; s++) {
            const int row = wm * 32 + (s >> 1) * 16 + (l >> 2) + (s & 1) * 8;
            rbuf[wn * 128 + row] = rs[s];
        }
    }
    __syncthreads();

    if (tid < 128) {
        g_rs[((size_t)sp * Hh + z) * Mq + bm + tid] = rbuf[tid] + rbuf[128 + tid];
    }

    if (wn == 0) {
        float* obase = g_Opart + (((size_t)sp * Hh + z) * Mq + bm) * Dd;
#pragma unroll
        for (int t = 0; t < 2; t++)
#pragma unroll
            for (int rh = 0; rh < 2; rh++) {
                const int row = wm * 32 + t * 16 + (l >> 2) + rh * 8;
#pragma unroll
                for (int nb = 0; nb < 16; nb++) {
                    const int col = nb * 8 + (l & 3) * 2;
                    float2 v = *(float2*)(obuf + row * 128 + col);
                    v.x += accO[t][nb][rh * 2 + 0];
                    v.y += accO[t][nb][rh * 2 + 1];
                    *(float2*)(obase + (size_t)row * Dd + col) = v;
                }
            }
    }
}

// ---------------- combine partials -> out ----------------
__global__ __launch_bounds__(256) void combine_kernel(float* __restrict__ outp)
{
    const size_t idx = (size_t)blockIdx.x * blockDim.x + threadIdx.x;
    const size_t e = idx * 4;
    const int m = (int)(e >> 12);
    const int c = (int)(e & (Nn - 1));
    const int h = c >> 7;
    const int d = c & 127;

    const size_t rbase = (size_t)h * Mq + m;
    const float tot = g_rs[rbase] + g_rs[(size_t)Hh * Mq + rbase]
                    + g_rs[2 * (size_t)Hh * Mq + rbase] + g_rs[3 * (size_t)Hh * Mq + rbase];
    const float inv = 1.0f / tot;

    const size_t pbase = ((size_t)h * Mq + m) * Dd + d;
    const size_t pstep = (size_t)Hh * Mq * Dd;
    float4 a = *(const float4*)(g_Opart + pbase);
    float4 b = *(const float4*)(g_Opart + pbase + pstep);
    float4 cc = *(const float4*)(g_Opart + pbase + 2 * pstep);
    float4 dd = *(const float4*)(g_Opart + pbase + 3 * pstep);
    float4 o;
    o.x = (a.x + b.x + cc.x + dd.x) * inv;
    o.y = (a.y + b.y + cc.y + dd.y) * inv;
    o.z = (a.z + b.z + cc.z + dd.z) * inv;
    o.w = (a.w + b.w + cc.w + dd.w) * inv;
    *(float4*)(outp + e) = o;
}

// ---------------- prep ----------------
__global__ __launch_bounds__(256) void convert_inputs(
    const float* __restrict__ X, const float* __restrict__ cK, const float* __restrict__ cV)
{
    const size_t stride = (size_t)gridDim.x * blockDim.x;
    const size_t tid0 = (size_t)blockIdx.x * blockDim.x + threadIdx.x;

    for (size_t i = tid0; i < (size_t)Mq * Nn; i += stride) {
        bf16 h, lo;
        split_bf16(X[i], h, lo);
        g_Xh[i] = h; g_Xl[i] = lo;
    }
    const size_t nkv = (size_t)Hh * Pp * Dd;
    for (size_t i = tid0; i < nkv; i += stride) {
        const size_t h = i / ((size_t)Pp * Dd);
        const size_t r = i % ((size_t)Pp * Dd);
        const size_t o = h * (size_t)NKEYS * Dd + r;
        bf16 hh, lo;
        split_bf16(cK[i], hh, lo);
        g_Kh[o] = hh; g_Kl[o] = lo;
        split_bf16(cV[i], hh, lo);
        g_Vh[o] = hh; g_Vl[o] = lo;
    }
}

// ---------------- host launcher ----------------
extern "C" void kernel_launch(void* const* d_in, const int* in_sizes, int n_in,
                              void* d_out, int out_size)
{
    const float* X  = (const float*)d_in[0];
    const float* Wq = (const float*)d_in[1];
    const float* Wk = (const float*)d_in[2];
    const float* Wv = (const float*)d_in[3];
    const float* cK = (const float*)d_in[4];
    const float* cV = (const float*)d_in[5];
    float* out = (float*)d_out;

    bf16 *xh, *xl;
    cudaGetSymbolAddress((void**)&xh, g_Xh);
    cudaGetSymbolAddress((void**)&xl, g_Xl);

    cudaFuncSetAttribute(proj_kernel, cudaFuncAttributeMaxDynamicSharedMemorySize, SMEM_PROJ);
    cudaFuncSetAttribute(attn_kernel, cudaFuncAttributeMaxDynamicSharedMemorySize, SMEM_ATT);

    convert_inputs<<<4096, 256>>>(X, cK, cV);

    proj_kernel<<<dim3(Nn / 128, Mq / 256, 3), 256, SMEM_PROJ>>>(xh, xl, Wq, Wk, Wv);

    attn_kernel<<<dim3(Mq / 128, Hh, NSPLIT), 256, SMEM_ATT>>>();

    combine_kernel<<<(Mq * Nn / 4) / 256, 256>>>(out);
}

// round 14
// speedup vs baseline: 1.0173x; 1.0092x over previous
#include <cuda_runtime.h>
#include <cuda_bf16.h>
#include <math.h>
#include <stdint.h>

#define Mq 1024
#define Nn 4096
#define Dd 128
#define Pp 3072
#define Hh 32
#define NKEYS 4096
#define NSPLIT 4
#define KEYB 64
#define NIT ((NKEYS / NSPLIT) / KEYB)   // 16
typedef __nv_bfloat16 bf16;

// ---------------- scratch ----------------
__device__ bf16 g_Xh[(size_t)Mq * Nn],       g_Xl[(size_t)Mq * Nn];
__device__ bf16 g_Qh[(size_t)Hh * Mq * Dd],  g_Ql[(size_t)Hh * Mq * Dd];
__device__ bf16 g_Kh[(size_t)Hh * NKEYS * Dd], g_Kl[(size_t)Hh * NKEYS * Dd];
__device__ bf16 g_Vh[(size_t)Hh * NKEYS * Dd], g_Vl[(size_t)Hh * NKEYS * Dd];
__device__ float g_Opart[(size_t)NSPLIT * Hh * Mq * Dd];
__device__ float g_rs[(size_t)NSPLIT * Hh * Mq];

// ---------------- helpers ----------------
static __device__ __forceinline__ uint32_t smem_u32(const void* p) {
    uint32_t a;
    asm("{ .reg .u64 t; cvta.to.shared.u64 t, %1; cvt.u32.u64 %0, t; }" : "=r"(a) : "l"(p));
    return a;
}
static __device__ __forceinline__ void cp_async16(uint32_t dst, const void* src) {
    asm volatile("cp.async.cg.shared.global [%0], [%1], 16;" :: "r"(dst), "l"(src));
}
#define CP_COMMIT() asm volatile("cp.async.commit_group;" ::: "memory")
#define CP_WAIT(n)  asm volatile("cp.async.wait_group %0;" :: "n"(n) : "memory")

static __device__ __forceinline__ void ldsm_x4(uint32_t& r0, uint32_t& r1, uint32_t& r2, uint32_t& r3,
                                               uint32_t addr) {
    asm volatile("ldmatrix.sync.aligned.m8n8.x4.shared.b16 {%0,%1,%2,%3}, [%4];"
                 : "=r"(r0), "=r"(r1), "=r"(r2), "=r"(r3) : "r"(addr));
}
static __device__ __forceinline__ void ldsm_x4_t(uint32_t& r0, uint32_t& r1, uint32_t& r2, uint32_t& r3,
                                                 uint32_t addr) {
    asm volatile("ldmatrix.sync.aligned.m8n8.x4.trans.shared.b16 {%0,%1,%2,%3}, [%4];"
                 : "=r"(r0), "=r"(r1), "=r"(r2), "=r"(r3) : "r"(addr));
}
static __device__ __forceinline__ void mma_bf16(float* c, const uint32_t* a, const uint32_t* b) {
    asm volatile(
        "mma.sync.aligned.m16n8k16.row.col.f32.bf16.bf16.f32 "
        "{%0,%1,%2,%3}, {%4,%5,%6,%7}, {%8,%9}, {%0,%1,%2,%3};"
        : "+f"(c[0]), "+f"(c[1]), "+f"(c[2]), "+f"(c[3])
        : "r"(a[0]), "r"(a[1]), "r"(a[2]), "r"(a[3]), "r"(b[0]), "r"(b[1]));
}
static __device__ __forceinline__ void split_bf16(float v, bf16& h, bf16& l) {
    h = __float2bfloat16(v);
    l = __float2bfloat16(v - __bfloat162float(h));
}
static __device__ __forceinline__ uint32_t cvt_bf16x2(float a, float b) {
    uint32_t r;
    asm("cvt.rn.bf16x2.f32 %0, %1, %2;" : "=r"(r) : "f"(b), "f"(a));
    return r;
}
static __device__ __forceinline__ void split_pair(float v0, float v1, uint32_t& ph, uint32_t& pl) {
    ph = cvt_bf16x2(v0, v1);
    const float h0 = __uint_as_float(ph << 16);
    const float h1 = __uint_as_float(ph & 0xFFFF0000u);
    pl = cvt_bf16x2(v0 - h0, v1 - h1);
}

// proj smem: rbuf 2048 | X stages 2x64KB | Wsplit 2x32KB = 198656
#define PROJ_XS   (2048)
#define PROJ_WS   (2048 + 131072)
#define SMEM_PROJ (2048 + 131072 + 65536)
// attn: rbuf 2048 | Q 64K (reused as O-reduce buf) | K ring 2x32K | V ring 2x32K
#define SMEM_ATT  (2048 + 65536 + 65536 + 65536)

// ---------------- projection GEMM: TM=256, TN=128, 256 thr, reg-staged W split ----------------
__global__ __launch_bounds__(256, 1) void proj_kernel(
    const bf16* __restrict__ Xh, const bf16* __restrict__ Xl,
    const float* __restrict__ Wq, const float* __restrict__ Wk, const float* __restrict__ Wv)
{
    extern __shared__ char smem[];
    float* rbuf = (float*)smem;
    const uint32_t sb = smem_u32(smem);
    const int tid = threadIdx.x;
    const int wid = tid >> 5, l = tid & 31;
    const int wm = wid >> 1, wn = wid & 1;
    const int bn = blockIdx.x * 128, bm = blockIdx.y * 256, z = blockIdx.z;

    const float* Wp = (z == 0) ? Wq : (z == 1) ? Wk : Wv;

    float acc[4][8][4];
#pragma unroll
    for (int t = 0; t < 4; t++)
#pragma unroll
        for (int nb = 0; nb < 8; nb++)
#pragma unroll
            for (int i = 0; i < 4; i++) acc[t][nb][i] = 0.f;

    const int nch = Nn >> 6;

    auto load_X = [&](int c) {
        const int k0 = c << 6;
        const uint32_t xb = sb + PROJ_XS + (c & 1) * 65536;
#pragma unroll
        for (int p = 0; p < 2; p++) {
            const bf16* src = p ? Xl : Xh;
#pragma unroll
            for (int i = tid; i < 2048; i += 256) {
                const int row = i >> 3, cc = i & 7;
                const uint32_t off = (uint32_t)(row * 128 + cc * 16);
                cp_async16(xb + p * 32768 + (off ^ (uint32_t)((row & 7) << 4)),
                           src + (size_t)(bm + row) * Nn + k0 + cc * 8);
            }
        }
        CP_COMMIT();
    };

    float4 w4[4];
    auto ldg_W = [&](int c) {
        const int k0 = c << 6;
#pragma unroll
        for (int j = 0; j < 4; j++) {
            const int i = tid + j * 256;          // 0..1023: row = i>>4 (64 rows), c16 = i&15? no:
            const int row = i >> 5, c16 = i & 31; // 2048 16B-units need 8 per thread... use 4x float4 of 2 units?
            (void)row; (void)c16;
            w4[j] = __ldg((const float4*)(Wp + (size_t)(k0 + (i >> 5)) * Nn + bn + (i & 31) * 4));
        }
    };
    // NOTE: 64 rows x 128 cols fp32 = 2048 float4's; 256 threads x 4 = 1024 — need 8.
    // Use 8 float4 regs instead (32 regs). Keep pressure acceptable by splitting into two halves.
    float4 w4b[4];
    auto ldg_W8 = [&](int c) {
        const int k0 = c << 6;
#pragma unroll
        for (int j = 0; j < 4; j++) {
            const int i = tid + j * 256;
            w4[j] = __ldg((const float4*)(Wp + (size_t)(k0 + (i >> 5)) * Nn + bn + (i & 31) * 4));
        }
#pragma unroll
        for (int j = 0; j < 4; j++) {
            const int i = tid + (j + 4) * 256;
            w4b[j] = __ldg((const float4*)(Wp + (size_t)(k0 + (i >> 5)) * Nn + bn + (i & 31) * 4));
        }
    };
    auto sts_W = [&](int buf) {
        char* ws = smem + PROJ_WS + buf * 32768;
#pragma unroll
        for (int j = 0; j < 8; j++) {
            const int i = tid + j * 256;
            const int row = i >> 5, c16 = i & 31;
            const float4 w = (j < 4) ? w4[j] : w4b[j - 4];
            uint32_t h01, l01, h23, l23;
            split_pair(w.x, w.y, h01, l01);
            split_pair(w.z, w.w, h23, l23);
            const uint32_t off = (uint32_t)(row * 256 + c16 * 8);
            const uint32_t sw = off ^ (uint32_t)((row & 7) << 4);
            *(uint2*)(ws + sw) = make_uint2(h01, h23);
            *(uint2*)(ws + 16384 + sw) = make_uint2(l01, l23);
        }
    };

    // prologue
    ldg_W8(0);
    load_X(0);
    load_X(1);
    CP_WAIT(1);
    __syncthreads();
    sts_W(0);          // Wsplit[0] <- W(0)
    ldg_W8(1);         // regs <- W(1)
    __syncthreads();   // Wsplit[0] visible

    for (int c = 0; c < nch; c++) {
        // invariant: X(c) ready+visible, Wsplit[c&1] ready+visible, regs hold W(c+1)
        if (c + 1 < nch) {
            sts_W((c + 1) & 1);                 // no barrier before MMA (different buffer)
            if (c + 2 < nch) ldg_W8(c + 2);
        }

        const uint32_t xb = sb + PROJ_XS + (c & 1) * 65536;
        const uint32_t wsb = sb + PROJ_WS + (c & 1) * 32768;
#pragma unroll
        for (int kk = 0; kk < 4; kk++) {
            uint32_t bH[8][2], bL[8][2];
#pragma unroll
            for (int bt = 0; bt < 4; bt++) {
                const int krow = kk * 16 + (l & 7) + ((l >> 3) & 1) * 8;
                const int colb = wn * 128 + bt * 32 + ((l >> 4) & 1) * 16;
                const uint32_t bo = (uint32_t)(krow * 256) + (uint32_t)(colb ^ ((krow & 7) << 4));
                ldsm_x4_t(bH[2 * bt][0], bH[2 * bt][1], bH[2 * bt + 1][0], bH[2 * bt + 1][1],
                          wsb + bo);
                ldsm_x4_t(bL[2 * bt][0], bL[2 * bt][1], bL[2 * bt + 1][0], bL[2 * bt + 1][1],
                          wsb + 16384 + bo);
            }
#pragma unroll
            for (int t = 0; t < 4; t++) {
                uint32_t aH[4], aL[4];
                const int mrow = wm * 64 + t * 16 + (l & 7) + ((l >> 3) & 1) * 8;
                const int kb = kk * 32 + ((l >> 4) & 1) * 16;
                const uint32_t ao = (uint32_t)(mrow * 128) + (uint32_t)(kb ^ ((mrow & 7) << 4));
                ldsm_x4(aH[0], aH[1], aH[2], aH[3], xb + ao);
                ldsm_x4(aL[0], aL[1], aL[2], aL[3], xb + 32768 + ao);
#pragma unroll
                for (int nb = 0; nb < 8; nb++) {
                    mma_bf16(acc[t][nb], aH, bH[nb]);
                    mma_bf16(acc[t][nb], aH, bL[nb]);
                    mma_bf16(acc[t][nb], aL, bH[nb]);
                }
            }
        }

        if (c + 1 < nch) {
            __syncthreads();                    // all warps done MMA(c)
            if (c + 2 < nch) load_X(c + 2); else CP_COMMIT();
            CP_WAIT(1);                         // X(c+1) complete
            __syncthreads();                    // X(c+1) + Wsplit[(c+1)&1] visible
        }
    }

    __syncthreads();
    if (z < 2) {
        float ss[8];
#pragma unroll
        for (int s = 0; s < 8; s++) ss[s] = 0.f;
#pragma unroll
        for (int t = 0; t < 4; t++)
#pragma unroll
            for (int nb = 0; nb < 8; nb++)
#pragma unroll
                for (int i = 0; i < 4; i++) {
                    const float v = acc[t][nb][i];
                    ss[t * 2 + (i >> 1)] += v * v;
                }
#pragma unroll
        for (int s = 0; s < 8; s++) {
            ss[s] += __shfl_xor_sync(0xffffffffu, ss[s], 1);
            ss[s] += __shfl_xor_sync(0xffffffffu, ss[s], 2);
        }
        if ((l & 3) == 0) {
#pragma unroll
            for (int s = 0; s < 8; s++) {
                const int row = wm * 64 + (s >> 1) * 16 + (l >> 2) + (s & 1) * 8;
                rbuf[wn * 256 + row] = ss[s];
            }
        }
        __syncthreads();
    }

    bf16* dh = (z == 0) ? g_Qh : (z == 1) ? g_Kh : g_Vh;
    bf16* dl = (z == 0) ? g_Ql : (z == 1) ? g_Kl : g_Vl;
#pragma unroll
    for (int t = 0; t < 4; t++)
#pragma unroll
        for (int rh = 0; rh < 2; rh++) {
            const int row = wm * 64 + t * 16 + (l >> 2) + rh * 8;
            float sc = 1.0f;
            if (z < 2) sc = rsqrtf((rbuf[row] + rbuf[256 + row]) * (1.0f / 128.0f));
            const size_t rowbase = (z == 0)
                ? ((size_t)blockIdx.x * Mq + bm + row) * 128
                : ((size_t)blockIdx.x * NKEYS + Pp + bm + row) * 128;
#pragma unroll
            for (int nb = 0; nb < 8; nb++) {
                const int col = wn * 64 + nb * 8 + (l & 3) * 2;
                uint32_t ph, pl;
                split_pair(acc[t][nb][rh * 2 + 0] * sc, acc[t][nb][rh * 2 + 1] * sc, ph, pl);
                *(uint32_t*)(dh + rowbase + col) = ph;
                *(uint32_t*)(dl + rowbase + col) = pl;
            }
        }
}

// ---------------- fused flash attention: register-resident P (R13, unchanged) ----------------
__global__ __launch_bounds__(256, 1) void attn_kernel()
{
    extern __shared__ char smem[];
    float* rbuf = (float*)smem;
    const uint32_t sb = smem_u32(smem);
    const uint32_t Qb = sb + 2048;
    const uint32_t Kr = Qb + 65536;
    const uint32_t Vr = Kr + 65536;

    const int tid = threadIdx.x;
    const int wid = tid >> 5, l = tid & 31;
    const int wm = wid >> 1, wn = wid & 1;
    const int bm = blockIdx.x * 128;
    const int z = blockIdx.y;
    const int sp = blockIdx.z;
    const int key0 = sp * (NKEYS / NSPLIT);

    const bf16* Qhp = g_Qh + ((size_t)z * Mq + bm) * Dd;
    const bf16* Qlp = g_Ql + ((size_t)z * Mq + bm) * Dd;
    const bf16* Khp = g_Kh + (size_t)z * NKEYS * Dd;
    const bf16* Klp = g_Kl + (size_t)z * NKEYS * Dd;
    const bf16* Vhp = g_Vh + (size_t)z * NKEYS * Dd;
    const bf16* Vlp = g_Vl + (size_t)z * NKEYS * Dd;

    auto load_Q = [&]() {
#pragma unroll
        for (int j = 0; j < 16; j++) {
            const int i = tid + j * 256;
            const int plane = i >> 10, row = (i >> 3) & 127, cc = i & 7;
            const bf16* src = (plane < 2) ? Qhp : Qlp;
            const int k0 = (plane & 1) * 64;
            const uint32_t off = (uint32_t)(row * 128 + cc * 16);
            cp_async16(Qb + plane * 16384 + (off ^ (uint32_t)((row & 7) << 4)),
                       src + (size_t)row * Dd + k0 + cc * 8);
        }
    };
    auto load_K = [&](int buf, int krow0) {
#pragma unroll
        for (int j = 0; j < 8; j++) {
            const int i = tid + j * 256;
            const int plane = i >> 9, row = (i >> 3) & 63, cc = i & 7;
            const bf16* src = (plane < 2) ? Khp : Klp;
            const int k0 = (plane & 1) * 64;
            const uint32_t off = (uint32_t)(row * 128 + cc * 16);
            cp_async16(Kr + buf * 32768 + plane * 8192 + (off ^ (uint32_t)((row & 7) << 4)),
                       src + (size_t)(krow0 + row) * Dd + k0 + cc * 8);
        }
    };
    auto load_V = [&](int buf, int krow0) {
#pragma unroll
        for (int j = 0; j < 8; j++) {
            const int i = tid + j * 256;
            const int plane = i >> 10, row = (i >> 4) & 63, c16 = i & 15;
            const bf16* src = plane ? Vlp : Vhp;
            const uint32_t off = (uint32_t)(row * 256 + c16 * 16);
            cp_async16(Vr + buf * 32768 + plane * 16384 + (off ^ (uint32_t)((row & 7) << 4)),
                       src + (size_t)(krow0 + row) * Dd + c16 * 8);
        }
    };

    auto do_mma_qk = [&](float acc[2][4][4], uint32_t kbuf) {
#pragma unroll
        for (int c = 0; c < 2; c++) {
            const uint32_t aHb = Qb + c * 16384, aLb = Qb + 32768 + c * 16384;
            const uint32_t bHb = kbuf + c * 8192, bLb = kbuf + 16384 + c * 8192;
#pragma unroll
            for (int kk = 0; kk < 4; kk++) {
                uint32_t aH[2][4], aL[2][4];
#pragma unroll
                for (int t = 0; t < 2; t++) {
                    const int mrow = wm * 32 + t * 16 + (l & 7) + ((l >> 3) & 1) * 8;
                    const int kb = kk * 32 + ((l >> 4) & 1) * 16;
                    const uint32_t ao = (uint32_t)(mrow * 128) + (uint32_t)(kb ^ ((mrow & 7) << 4));
                    ldsm_x4(aH[t][0], aH[t][1], aH[t][2], aH[t][3], aHb + ao);
                    ldsm_x4(aL[t][0], aL[t][1], aL[t][2], aL[t][3], aLb + ao);
                }
                uint32_t bH[4][2], bL[4][2];
#pragma unroll
                for (int bt = 0; bt < 2; bt++) {
                    const int nrow = wn * 32 + bt * 16 + (l & 7) + ((l >> 4) & 1) * 8;
                    const int kb = kk * 32 + ((l >> 3) & 1) * 16;
                    const uint32_t bo = (uint32_t)(nrow * 128) + (uint32_t)(kb ^ ((nrow & 7) << 4));
                    ldsm_x4(bH[2 * bt][0], bH[2 * bt][1], bH[2 * bt + 1][0], bH[2 * bt + 1][1], bHb + bo);
                    ldsm_x4(bL[2 * bt][0], bL[2 * bt][1], bL[2 * bt + 1][0], bL[2 * bt + 1][1], bLb + bo);
                }
#pragma unroll
                for (int t = 0; t < 2; t++)
#pragma unroll
                    for (int nb = 0; nb < 4; nb++) {
                        mma_bf16(acc[t][nb], aH[t], bH[nb]);
                        mma_bf16(acc[t][nb], aH[t], bL[nb]);
                        mma_bf16(acc[t][nb], aL[t], bH[nb]);
                    }
            }
        }
    };

    float accO[2][16][4];
#pragma unroll
    for (int t = 0; t < 2; t++)
#pragma unroll
        for (int nb = 0; nb < 16; nb++)
#pragma unroll
            for (int i = 0; i < 4; i++) accO[t][nb][i] = 0.f;
    float rs[4] = {0.f, 0.f, 0.f, 0.f};

    load_Q();
    load_K(0, key0);
    load_V(0, key0);
    CP_COMMIT();

    for (int it = 0; it < NIT; it++) {
        CP_WAIT(0);
        __syncthreads();

        if (it + 1 < NIT) {
            load_K((it + 1) & 1, key0 + (it + 1) * KEYB);
            load_V((it + 1) & 1, key0 + (it + 1) * KEYB);
        }
        CP_COMMIT();

        float accS[2][4][4];
#pragma unroll
        for (int t = 0; t < 2; t++)
#pragma unroll
            for (int nb = 0; nb < 4; nb++)
#pragma unroll
                for (int i = 0; i < 4; i++) accS[t][nb][i] = 0.f;

        do_mma_qk(accS, Kr + (it & 1) * 32768);

        uint32_t pH[2][4][2], pL[2][4][2];
#pragma unroll
        for (int t = 0; t < 2; t++)
#pragma unroll
            for (int nb = 0; nb < 4; nb++)
#pragma unroll
                for (int rh = 0; rh < 2; rh++) {
                    const float e0 = __expf(accS[t][nb][rh * 2 + 0]);
                    const float e1 = __expf(accS[t][nb][rh * 2 + 1]);
                    rs[t * 2 + rh] += e0 + e1;
                    split_pair(e0, e1, pH[t][nb][rh], pL[t][nb][rh]);
                }

        const uint32_t vbuf = Vr + (it & 1) * 32768;
#pragma unroll
        for (int st = 0; st < 2; st++) {
            uint32_t aH[2][4], aL[2][4];
#pragma unroll
            for (int t = 0; t < 2; t++) {
                aH[t][0] = pH[t][2 * st][0];
                aH[t][1] = pH[t][2 * st][1];
                aH[t][2] = pH[t][2 * st + 1][0];
                aH[t][3] = pH[t][2 * st + 1][1];
                aL[t][0] = pL[t][2 * st][0];
                aL[t][1] = pL[t][2 * st][1];
                aL[t][2] = pL[t][2 * st + 1][0];
                aL[t][3] = pL[t][2 * st + 1][1];
            }
            const int key = (wn * 2 + st) * 16 + (l & 7) + ((l >> 3) & 1) * 8;
#pragma unroll
            for (int bt = 0; bt < 8; bt++) {
                const int colb = bt * 32 + ((l >> 4) & 1) * 16;
                const uint32_t bo = (uint32_t)(key * 256) + (uint32_t)(colb ^ ((key & 7) << 4));
                uint32_t bH[2][2], bL[2][2];
                ldsm_x4_t(bH[0][0], bH[0][1], bH[1][0], bH[1][1], vbuf + bo);
                ldsm_x4_t(bL[0][0], bL[0][1], bL[1][0], bL[1][1], vbuf + 16384 + bo);
#pragma unroll
                for (int t = 0; t < 2; t++)
#pragma unroll
                    for (int j = 0; j < 2; j++) {
                        mma_bf16(accO[t][2 * bt + j], aH[t], bH[j]);
                        mma_bf16(accO[t][2 * bt + j], aH[t], bL[j]);
                        mma_bf16(accO[t][2 * bt + j], aL[t], bH[j]);
                    }
            }
        }
        __syncthreads();
    }

    float* obuf = (float*)(smem + 2048);

    if (wn == 1) {
#pragma unroll
        for (int t = 0; t < 2; t++)
#pragma unroll
            for (int rh = 0; rh < 2; rh++) {
                const int row = wm * 32 + t * 16 + (l >> 2) + rh * 8;
#pragma unroll
                for (int nb = 0; nb < 16; nb++) {
                    const int col = nb * 8 + (l & 3) * 2;
                    float2 v;
                    v.x = accO[t][nb][rh * 2 + 0];
                    v.y = accO[t][nb][rh * 2 + 1];
                    *(float2*)(obuf + row * 128 + col) = v;
                }
            }
    }

#pragma unroll
    for (int s = 0; s < 4; s++) {
        rs[s] += __shfl_xor_sync(0xffffffffu, rs[s], 1);
        rs[s] += __shfl_xor_sync(0xffffffffu, rs[s], 2);
    }
    __syncthreads();

    if ((l & 3) == 0) {
#pragma unroll
        for (int s = 0; s < 4; s++) {
            const int row = wm * 32 + (s >> 1) * 16 + (l >> 2) + (s & 1) * 8;
            rbuf[wn * 128 + row] = rs[s];
        }
    }
    __syncthreads();

    if (tid < 128) {
        g_rs[((size_t)sp * Hh + z) * Mq + bm + tid] = rbuf[tid] + rbuf[128 + tid];
    }

    if (wn == 0) {
        float* obase = g_Opart + (((size_t)sp * Hh + z) * Mq + bm) * Dd;
#pragma unroll
        for (int t = 0; t < 2; t++)
#pragma unroll
            for (int rh = 0; rh < 2; rh++) {
                const int row = wm * 32 + t * 16 + (l >> 2) + rh * 8;
#pragma unroll
                for (int nb = 0; nb < 16; nb++) {
                    const int col = nb * 8 + (l & 3) * 2;
                    float2 v = *(float2*)(obuf + row * 128 + col);
                    v.x += accO[t][nb][rh * 2 + 0];
                    v.y += accO[t][nb][rh * 2 + 1];
                    *(float2*)(obase + (size_t)row * Dd + col) = v;
                }
            }
    }
}

// ---------------- combine partials -> out ----------------
__global__ __launch_bounds__(256) void combine_kernel(float* __restrict__ outp)
{
    const size_t idx = (size_t)blockIdx.x * blockDim.x + threadIdx.x;
    const size_t e = idx * 4;
    const int m = (int)(e >> 12);
    const int c = (int)(e & (Nn - 1));
    const int h = c >> 7;
    const int d = c & 127;

    const size_t rbase = (size_t)h * Mq + m;
    const float tot = g_rs[rbase] + g_rs[(size_t)Hh * Mq + rbase]
                    + g_rs[2 * (size_t)Hh * Mq + rbase] + g_rs[3 * (size_t)Hh * Mq + rbase];
    const float inv = 1.0f / tot;

    const size_t pbase = ((size_t)h * Mq + m) * Dd + d;
    const size_t pstep = (size_t)Hh * Mq * Dd;
    float4 a = *(const float4*)(g_Opart + pbase);
    float4 b = *(const float4*)(g_Opart + pbase + pstep);
    float4 cc = *(const float4*)(g_Opart + pbase + 2 * pstep);
    float4 dd = *(const float4*)(g_Opart + pbase + 3 * pstep);
    float4 o;
    o.x = (a.x + b.x + cc.x + dd.x) * inv;
    o.y = (a.y + b.y + cc.y + dd.y) * inv;
    o.z = (a.z + b.z + cc.z + dd.z) * inv;
    o.w = (a.w + b.w + cc.w + dd.w) * inv;
    *(float4*)(outp + e) = o;
}

// ---------------- prep ----------------
__global__ __launch_bounds__(256) void convert_inputs(
    const float* __restrict__ X, const float* __restrict__ cK, const float* __restrict__ cV)
{
    const size_t stride = (size_t)gridDim.x * blockDim.x;
    const size_t tid0 = (size_t)blockIdx.x * blockDim.x + threadIdx.x;

    for (size_t i = tid0; i < (size_t)Mq * Nn; i += stride) {
        bf16 h, lo;
        split_bf16(X[i], h, lo);
        g_Xh[i] = h; g_Xl[i] = lo;
    }
    const size_t nkv = (size_t)Hh * Pp * Dd;
    for (size_t i = tid0; i < nkv; i += stride) {
        const size_t h = i / ((size_t)Pp * Dd);
        const size_t r = i % ((size_t)Pp * Dd);
        const size_t o = h * (size_t)NKEYS * Dd + r;
        bf16 hh, lo;
        split_bf16(cK[i], hh, lo);
        g_Kh[o] = hh; g_Kl[o] = lo;
        split_bf16(cV[i], hh, lo);
        g_Vh[o] = hh; g_Vl[o] = lo;
    }
}

// ---------------- host launcher ----------------
extern "C" void kernel_launch(void* const* d_in, const int* in_sizes, int n_in,
                              void* d_out, int out_size)
{
    const float* X  = (const float*)d_in[0];
    const float* Wq = (const float*)d_in[1];
    const float* Wk = (const float*)d_in[2];
    const float* Wv = (const float*)d_in[3];
    const float* cK = (const float*)d_in[4];
    const float* cV = (const float*)d_in[5];
    float* out = (float*)d_out;

    bf16 *xh, *xl;
    cudaGetSymbolAddress((void**)&xh, g_Xh);
    cudaGetSymbolAddress((void**)&xl, g_Xl);

    cudaFuncSetAttribute(proj_kernel, cudaFuncAttributeMaxDynamicSharedMemorySize, SMEM_PROJ);
    cudaFuncSetAttribute(attn_kernel, cudaFuncAttributeMaxDynamicSharedMemorySize, SMEM_ATT);

    convert_inputs<<<4096, 256>>>(X, cK, cV);

    proj_kernel<<<dim3(Nn / 128, Mq / 256, 3), 256, SMEM_PROJ>>>(xh, xl, Wq, Wk, Wv);

    attn_kernel<<<dim3(Mq / 128, Hh, NSPLIT), 256, SMEM_ATT>>>();

    combine_kernel<<<(Mq * Nn / 4) / 256, 256>>>(out);
}

// round 15
// speedup vs baseline: 1.0178x; 1.0005x over previous
#include <cuda_runtime.h>
#include <cuda_bf16.h>
#include <math.h>
#include <stdint.h>

#define Mq 1024
#define Nn 4096
#define Dd 128
#define Pp 3072
#define Hh 32
#define NKEYS 4096
#define NSPLIT 4
#define KEYB 64
#define NIT ((NKEYS / NSPLIT) / KEYB)   // 16
#define LOG2E 1.4426950408889634f
typedef __nv_bfloat16 bf16;

// ---------------- scratch ----------------
__device__ bf16 g_Xh[(size_t)Mq * Nn],       g_Xl[(size_t)Mq * Nn];
__device__ bf16 g_Qh[(size_t)Hh * Mq * Dd],  g_Ql[(size_t)Hh * Mq * Dd];
__device__ bf16 g_Kh[(size_t)Hh * NKEYS * Dd], g_Kl[(size_t)Hh * NKEYS * Dd];
__device__ bf16 g_Vh[(size_t)Hh * NKEYS * Dd], g_Vl[(size_t)Hh * NKEYS * Dd];
__device__ float g_Opart[(size_t)NSPLIT * Hh * Mq * Dd];
__device__ float g_rs[(size_t)NSPLIT * Hh * Mq];

// ---------------- helpers ----------------
static __device__ __forceinline__ uint32_t smem_u32(const void* p) {
    uint32_t a;
    asm("{ .reg .u64 t; cvta.to.shared.u64 t, %1; cvt.u32.u64 %0, t; }" : "=r"(a) : "l"(p));
    return a;
}
static __device__ __forceinline__ void cp_async16(uint32_t dst, const void* src) {
    asm volatile("cp.async.cg.shared.global [%0], [%1], 16;" :: "r"(dst), "l"(src));
}
#define CP_COMMIT() asm volatile("cp.async.commit_group;" ::: "memory")
#define CP_WAIT(n)  asm volatile("cp.async.wait_group %0;" :: "n"(n) : "memory")

static __device__ __forceinline__ void ldsm_x4(uint32_t& r0, uint32_t& r1, uint32_t& r2, uint32_t& r3,
                                               uint32_t addr) {
    asm volatile("ldmatrix.sync.aligned.m8n8.x4.shared.b16 {%0,%1,%2,%3}, [%4];"
                 : "=r"(r0), "=r"(r1), "=r"(r2), "=r"(r3) : "r"(addr));
}
static __device__ __forceinline__ void ldsm_x4_t(uint32_t& r0, uint32_t& r1, uint32_t& r2, uint32_t& r3,
                                                 uint32_t addr) {
    asm volatile("ldmatrix.sync.aligned.m8n8.x4.trans.shared.b16 {%0,%1,%2,%3}, [%4];"
                 : "=r"(r0), "=r"(r1), "=r"(r2), "=r"(r3) : "r"(addr));
}
static __device__ __forceinline__ void mma_bf16(float* c, const uint32_t* a, const uint32_t* b) {
    asm volatile(
        "mma.sync.aligned.m16n8k16.row.col.f32.bf16.bf16.f32 "
        "{%0,%1,%2,%3}, {%4,%5,%6,%7}, {%8,%9}, {%0,%1,%2,%3};"
        : "+f"(c[0]), "+f"(c[1]), "+f"(c[2]), "+f"(c[3])
        : "r"(a[0]), "r"(a[1]), "r"(a[2]), "r"(a[3]), "r"(b[0]), "r"(b[1]));
}
static __device__ __forceinline__ void split_bf16(float v, bf16& h, bf16& l) {
    h = __float2bfloat16(v);
    l = __float2bfloat16(v - __bfloat162float(h));
}
static __device__ __forceinline__ uint32_t cvt_bf16x2(float a, float b) {
    uint32_t r;
    asm("cvt.rn.bf16x2.f32 %0, %1, %2;" : "=r"(r) : "f"(b), "f"(a));
    return r;
}
static __device__ __forceinline__ void split_pair(float v0, float v1, uint32_t& ph, uint32_t& pl) {
    ph = cvt_bf16x2(v0, v1);
    const float h0 = __uint_as_float(ph << 16);
    const float h1 = __uint_as_float(ph & 0xFFFF0000u);
    pl = cvt_bf16x2(v0 - h0, v1 - h1);
}
static __device__ __forceinline__ float ex2(float x) {
    float r;
    asm("ex2.approx.f32 %0, %1;" : "=f"(r) : "f"(x));
    return r;
}

// proj smem: rbuf 2048 | X stages 2x64KB | Wsplit 2x32KB
#define PROJ_XS   (2048)
#define PROJ_WS   (2048 + 131072)
#define SMEM_PROJ (2048 + 131072 + 65536)
// attn: rbuf 2048 | Q 64K (reused as O-reduce buf) | K ring 2x32K | V ring 2x32K
#define SMEM_ATT  (2048 + 65536 + 65536 + 65536)

// ---------------- projection GEMM: TM=256, TN=128, 256 thr, reg-staged W split ----------------
__global__ __launch_bounds__(256, 1) void proj_kernel(
    const bf16* __restrict__ Xh, const bf16* __restrict__ Xl,
    const float* __restrict__ Wq, const float* __restrict__ Wk, const float* __restrict__ Wv)
{
    extern __shared__ char smem[];
    float* rbuf = (float*)smem;
    const uint32_t sb = smem_u32(smem);
    const int tid = threadIdx.x;
    const int wid = tid >> 5, l = tid & 31;
    const int wm = wid >> 1, wn = wid & 1;
    const int bn = blockIdx.x * 128, bm = blockIdx.y * 256, z = blockIdx.z;

    const float* Wp = (z == 0) ? Wq : (z == 1) ? Wk : Wv;

    float acc[4][8][4];
#pragma unroll
    for (int t = 0; t < 4; t++)
#pragma unroll
        for (int nb = 0; nb < 8; nb++)
#pragma unroll
            for (int i = 0; i < 4; i++) acc[t][nb][i] = 0.f;

    const int nch = Nn >> 6;

    auto load_X = [&](int c) {
        const int k0 = c << 6;
        const uint32_t xb = sb + PROJ_XS + (c & 1) * 65536;
#pragma unroll
        for (int p = 0; p < 2; p++) {
            const bf16* src = p ? Xl : Xh;
#pragma unroll
            for (int i = tid; i < 2048; i += 256) {
                const int row = i >> 3, cc = i & 7;
                const uint32_t off = (uint32_t)(row * 128 + cc * 16);
                cp_async16(xb + p * 32768 + (off ^ (uint32_t)((row & 7) << 4)),
                           src + (size_t)(bm + row) * Nn + k0 + cc * 8);
            }
        }
        CP_COMMIT();
    };

    float4 w4[4], w4b[4];
    auto ldg_W8 = [&](int c) {
        const int k0 = c << 6;
#pragma unroll
        for (int j = 0; j < 4; j++) {
            const int i = tid + j * 256;
            w4[j] = __ldg((const float4*)(Wp + (size_t)(k0 + (i >> 5)) * Nn + bn + (i & 31) * 4));
        }
#pragma unroll
        for (int j = 0; j < 4; j++) {
            const int i = tid + (j + 4) * 256;
            w4b[j] = __ldg((const float4*)(Wp + (size_t)(k0 + (i >> 5)) * Nn + bn + (i & 31) * 4));
        }
    };
    auto sts_W = [&](int buf) {
        char* ws = smem + PROJ_WS + buf * 32768;
#pragma unroll
        for (int j = 0; j < 8; j++) {
            const int i = tid + j * 256;
            const int row = i >> 5, c16 = i & 31;
            const float4 w = (j < 4) ? w4[j] : w4b[j - 4];
            uint32_t h01, l01, h23, l23;
            split_pair(w.x, w.y, h01, l01);
            split_pair(w.z, w.w, h23, l23);
            const uint32_t off = (uint32_t)(row * 256 + c16 * 8);
            const uint32_t sw = off ^ (uint32_t)((row & 7) << 4);
            *(uint2*)(ws + sw) = make_uint2(h01, h23);
            *(uint2*)(ws + 16384 + sw) = make_uint2(l01, l23);
        }
    };

    ldg_W8(0);
    load_X(0);
    load_X(1);
    CP_WAIT(1);
    __syncthreads();
    sts_W(0);
    ldg_W8(1);
    __syncthreads();

    for (int c = 0; c < nch; c++) {
        if (c + 1 < nch) {
            sts_W((c + 1) & 1);
            if (c + 2 < nch) ldg_W8(c + 2);
        }

        const uint32_t xb = sb + PROJ_XS + (c & 1) * 65536;
        const uint32_t wsb = sb + PROJ_WS + (c & 1) * 32768;
#pragma unroll
        for (int kk = 0; kk < 4; kk++) {
            uint32_t bH[8][2], bL[8][2];
#pragma unroll
            for (int bt = 0; bt < 4; bt++) {
                const int krow = kk * 16 + (l & 7) + ((l >> 3) & 1) * 8;
                const int colb = wn * 128 + bt * 32 + ((l >> 4) & 1) * 16;
                const uint32_t bo = (uint32_t)(krow * 256) + (uint32_t)(colb ^ ((krow & 7) << 4));
                ldsm_x4_t(bH[2 * bt][0], bH[2 * bt][1], bH[2 * bt + 1][0], bH[2 * bt + 1][1],
                          wsb + bo);
                ldsm_x4_t(bL[2 * bt][0], bL[2 * bt][1], bL[2 * bt + 1][0], bL[2 * bt + 1][1],
                          wsb + 16384 + bo);
            }
#pragma unroll
            for (int t = 0; t < 4; t++) {
                uint32_t aH[4], aL[4];
                const int mrow = wm * 64 + t * 16 + (l & 7) + ((l >> 3) & 1) * 8;
                const int kb = kk * 32 + ((l >> 4) & 1) * 16;
                const uint32_t ao = (uint32_t)(mrow * 128) + (uint32_t)(kb ^ ((mrow & 7) << 4));
                ldsm_x4(aH[0], aH[1], aH[2], aH[3], xb + ao);
                ldsm_x4(aL[0], aL[1], aL[2], aL[3], xb + 32768 + ao);
#pragma unroll
                for (int nb = 0; nb < 8; nb++) {
                    mma_bf16(acc[t][nb], aH, bH[nb]);
                    mma_bf16(acc[t][nb], aH, bL[nb]);
                    mma_bf16(acc[t][nb], aL, bH[nb]);
                }
            }
        }

        if (c + 1 < nch) {
            __syncthreads();
            if (c + 2 < nch) load_X(c + 2); else CP_COMMIT();
            CP_WAIT(1);
            __syncthreads();
        }
    }

    __syncthreads();
    if (z < 2) {
        float ss[8];
#pragma unroll
        for (int s = 0; s < 8; s++) ss[s] = 0.f;
#pragma unroll
        for (int t = 0; t < 4; t++)
#pragma unroll
            for (int nb = 0; nb < 8; nb++)
#pragma unroll
                for (int i = 0; i < 4; i++) {
                    const float v = acc[t][nb][i];
                    ss[t * 2 + (i >> 1)] += v * v;
                }
#pragma unroll
        for (int s = 0; s < 8; s++) {
            ss[s] += __shfl_xor_sync(0xffffffffu, ss[s], 1);
            ss[s] += __shfl_xor_sync(0xffffffffu, ss[s], 2);
        }
        if ((l & 3) == 0) {
#pragma unroll
            for (int s = 0; s < 8; s++) {
                const int row = wm * 64 + (s >> 1) * 16 + (l >> 2) + (s & 1) * 8;
                rbuf[wn * 256 + row] = ss[s];
            }
        }
        __syncthreads();
    }

    bf16* dh = (z == 0) ? g_Qh : (z == 1) ? g_Kh : g_Vh;
    bf16* dl = (z == 0) ? g_Ql : (z == 1) ? g_Kl : g_Vl;
#pragma unroll
    for (int t = 0; t < 4; t++)
#pragma unroll
        for (int rh = 0; rh < 2; rh++) {
            const int row = wm * 64 + t * 16 + (l >> 2) + rh * 8;
            float sc = 1.0f;
            if (z < 2) sc = rsqrtf((rbuf[row] + rbuf[256 + row]) * (1.0f / 128.0f));
            if (z == 0) sc *= LOG2E;                 // prescale Q: attn uses exp2
            const size_t rowbase = (z == 0)
                ? ((size_t)blockIdx.x * Mq + bm + row) * 128
                : ((size_t)blockIdx.x * NKEYS + Pp + bm + row) * 128;
#pragma unroll
            for (int nb = 0; nb < 8; nb++) {
                const int col = wn * 64 + nb * 8 + (l & 3) * 2;
                uint32_t ph, pl;
                split_pair(acc[t][nb][rh * 2 + 0] * sc, acc[t][nb][rh * 2 + 1] * sc, ph, pl);
                *(uint32_t*)(dh + rowbase + col) = ph;
                *(uint32_t*)(dl + rowbase + col) = pl;
            }
        }
}

// ---------------- fused flash attention: register-resident P, exp2, 1 sync/iter ----------------
__global__ __launch_bounds__(256, 1) void attn_kernel()
{
    extern __shared__ char smem[];
    float* rbuf = (float*)smem;
    const uint32_t sb = smem_u32(smem);
    const uint32_t Qb = sb + 2048;
    const uint32_t Kr = Qb + 65536;
    const uint32_t Vr = Kr + 65536;

    const int tid = threadIdx.x;
    const int wid = tid >> 5, l = tid & 31;
    const int wm = wid >> 1, wn = wid & 1;
    const int bm = blockIdx.x * 128;
    const int z = blockIdx.y;
    const int sp = blockIdx.z;
    const int key0 = sp * (NKEYS / NSPLIT);

    const bf16* Qhp = g_Qh + ((size_t)z * Mq + bm) * Dd;
    const bf16* Qlp = g_Ql + ((size_t)z * Mq + bm) * Dd;
    const bf16* Khp = g_Kh + (size_t)z * NKEYS * Dd;
    const bf16* Klp = g_Kl + (size_t)z * NKEYS * Dd;
    const bf16* Vhp = g_Vh + (size_t)z * NKEYS * Dd;
    const bf16* Vlp = g_Vl + (size_t)z * NKEYS * Dd;

    auto load_Q = [&]() {
#pragma unroll
        for (int j = 0; j < 16; j++) {
            const int i = tid + j * 256;
            const int plane = i >> 10, row = (i >> 3) & 127, cc = i & 7;
            const bf16* src = (plane < 2) ? Qhp : Qlp;
            const int k0 = (plane & 1) * 64;
            const uint32_t off = (uint32_t)(row * 128 + cc * 16);
            cp_async16(Qb + plane * 16384 + (off ^ (uint32_t)((row & 7) << 4)),
                       src + (size_t)row * Dd + k0 + cc * 8);
        }
    };
    auto load_K = [&](int buf, int krow0) {
#pragma unroll
        for (int j = 0; j < 8; j++) {
            const int i = tid + j * 256;
            const int plane = i >> 9, row = (i >> 3) & 63, cc = i & 7;
            const bf16* src = (plane < 2) ? Khp : Klp;
            const int k0 = (plane & 1) * 64;
            const uint32_t off = (uint32_t)(row * 128 + cc * 16);
            cp_async16(Kr + buf * 32768 + plane * 8192 + (off ^ (uint32_t)((row & 7) << 4)),
                       src + (size_t)(krow0 + row) * Dd + k0 + cc * 8);
        }
    };
    auto load_V = [&](int buf, int krow0) {
#pragma unroll
        for (int j = 0; j < 8; j++) {
            const int i = tid + j * 256;
            const int plane = i >> 10, row = (i >> 4) & 63, c16 = i & 15;
            const bf16* src = plane ? Vlp : Vhp;
            const uint32_t off = (uint32_t)(row * 256 + c16 * 16);
            cp_async16(Vr + buf * 32768 + plane * 16384 + (off ^ (uint32_t)((row & 7) << 4)),
                       src + (size_t)(krow0 + row) * Dd + c16 * 8);
        }
    };

    auto do_mma_qk = [&](float acc[2][4][4], uint32_t kbuf) {
#pragma unroll
        for (int c = 0; c < 2; c++) {
            const uint32_t aHb = Qb + c * 16384, aLb = Qb + 32768 + c * 16384;
            const uint32_t bHb = kbuf + c * 8192, bLb = kbuf + 16384 + c * 8192;
#pragma unroll
            for (int kk = 0; kk < 4; kk++) {
                uint32_t aH[2][4], aL[2][4];
#pragma unroll
                for (int t = 0; t < 2; t++) {
                    const int mrow = wm * 32 + t * 16 + (l & 7) + ((l >> 3) & 1) * 8;
                    const int kb = kk * 32 + ((l >> 4) & 1) * 16;
                    const uint32_t ao = (uint32_t)(mrow * 128) + (uint32_t)(kb ^ ((mrow & 7) << 4));
                    ldsm_x4(aH[t][0], aH[t][1], aH[t][2], aH[t][3], aHb + ao);
                    ldsm_x4(aL[t][0], aL[t][1], aL[t][2], aL[t][3], aLb + ao);
                }
                uint32_t bH[4][2], bL[4][2];
#pragma unroll
                for (int bt = 0; bt < 2; bt++) {
                    const int nrow = wn * 32 + bt * 16 + (l & 7) + ((l >> 4) & 1) * 8;
                    const int kb = kk * 32 + ((l >> 3) & 1) * 16;
                    const uint32_t bo = (uint32_t)(nrow * 128) + (uint32_t)(kb ^ ((nrow & 7) << 4));
                    ldsm_x4(bH[2 * bt][0], bH[2 * bt][1], bH[2 * bt + 1][0], bH[2 * bt + 1][1], bHb + bo);
                    ldsm_x4(bL[2 * bt][0], bL[2 * bt][1], bL[2 * bt + 1][0], bL[2 * bt + 1][1], bLb + bo);
                }
#pragma unroll
                for (int t = 0; t < 2; t++)
#pragma unroll
                    for (int nb = 0; nb < 4; nb++) {
                        mma_bf16(acc[t][nb], aH[t], bH[nb]);
                        mma_bf16(acc[t][nb], aH[t], bL[nb]);
                        mma_bf16(acc[t][nb], aL[t], bH[nb]);
                    }
            }
        }
    };

    float accO[2][16][4];
#pragma unroll
    for (int t = 0; t < 2; t++)
#pragma unroll
        for (int nb = 0; nb < 16; nb++)
#pragma unroll
            for (int i = 0; i < 4; i++) accO[t][nb][i] = 0.f;
    float rs[4] = {0.f, 0.f, 0.f, 0.f};

    load_Q();
    load_K(0, key0);
    load_V(0, key0);
    CP_COMMIT();

    for (int it = 0; it < NIT; it++) {
        CP_WAIT(0);
        __syncthreads();          // K/V(it) visible; also: everyone finished PV(it-1)

        if (it + 1 < NIT) {
            load_K((it + 1) & 1, key0 + (it + 1) * KEYB);
            load_V((it + 1) & 1, key0 + (it + 1) * KEYB);
        }
        CP_COMMIT();

        float accS[2][4][4];
#pragma unroll
        for (int t = 0; t < 2; t++)
#pragma unroll
            for (int nb = 0; nb < 4; nb++)
#pragma unroll
                for (int i = 0; i < 4; i++) accS[t][nb][i] = 0.f;

        do_mma_qk(accS, Kr + (it & 1) * 32768);

        const uint32_t vbuf = Vr + (it & 1) * 32768;
        // st-interleaved: exp(st) feeds PV(st); exp(st=1) overlaps PV(st=0)
#pragma unroll
        for (int st = 0; st < 2; st++) {
            uint32_t aH[2][4], aL[2][4];
#pragma unroll
            for (int t = 0; t < 2; t++)
#pragma unroll
                for (int j = 0; j < 2; j++) {     // nb = 2*st + j
                    const int nb = 2 * st + j;
#pragma unroll
                    for (int rh = 0; rh < 2; rh++) {
                        const float e0 = ex2(accS[t][nb][rh * 2 + 0]);
                        const float e1 = ex2(accS[t][nb][rh * 2 + 1]);
                        rs[t * 2 + rh] += e0 + e1;
                        split_pair(e0, e1, aH[t][j * 2 + rh], aL[t][j * 2 + rh]);
                    }
                }
            const int key = (wn * 2 + st) * 16 + (l & 7) + ((l >> 3) & 1) * 8;
#pragma unroll
            for (int bt = 0; bt < 8; bt++) {
                const int colb = bt * 32 + ((l >> 4) & 1) * 16;
                const uint32_t bo = (uint32_t)(key * 256) + (uint32_t)(colb ^ ((key & 7) << 4));
                uint32_t bH[2][2], bL[2][2];
                ldsm_x4_t(bH[0][0], bH[0][1], bH[1][0], bH[1][1], vbuf + bo);
                ldsm_x4_t(bL[0][0], bL[0][1], bL[1][0], bL[1][1], vbuf + 16384 + bo);
#pragma unroll
                for (int t = 0; t < 2; t++)
#pragma unroll
                    for (int j = 0; j < 2; j++) {
                        mma_bf16(accO[t][2 * bt + j], aH[t], bH[j]);
                        mma_bf16(accO[t][2 * bt + j], aH[t], bL[j]);
                        mma_bf16(accO[t][2 * bt + j], aL[t], bH[j]);
                    }
            }
        }
        // no end-of-loop sync: next iter's top sync provides WAR protection
    }
    __syncthreads();   // all warps done with Q region + last PV before obuf reuse

    float* obuf = (float*)(smem + 2048);

    if (wn == 1) {
#pragma unroll
        for (int t = 0; t < 2; t++)
#pragma unroll
            for (int rh = 0; rh < 2; rh++) {
                const int row = wm * 32 + t * 16 + (l >> 2) + rh * 8;
#pragma unroll
                for (int nb = 0; nb < 16; nb++) {
                    const int col = nb * 8 + (l & 3) * 2;
                    float2 v;
                    v.x = accO[t][nb][rh * 2 + 0];
                    v.y = accO[t][nb][rh * 2 + 1];
                    *(float2*)(obuf + row * 128 + col) = v;
                }
            }
    }

#pragma unroll
    for (int s = 0; s < 4; s++) {
        rs[s] += __shfl_xor_sync(0xffffffffu, rs[s], 1);
        rs[s] += __shfl_xor_sync(0xffffffffu, rs[s], 2);
    }
    __syncthreads();

    if ((l & 3) == 0) {
#pragma unroll
        for (int s = 0; s < 4; s++) {
            const int row = wm * 32 + (s >> 1) * 16 + (l >> 2) + (s & 1) * 8;
            rbuf[wn * 128 + row] = rs[s];
        }
    }
    __syncthreads();

    if (tid < 128) {
        g_rs[((size_t)sp * Hh + z) * Mq + bm + tid] = rbuf[tid] + rbuf[128 + tid];
    }

    if (wn == 0) {
        float* obase = g_Opart + (((size_t)sp * Hh + z) * Mq + bm) * Dd;
#pragma unroll
        for (int t = 0; t < 2; t++)
#pragma unroll
            for (int rh = 0; rh < 2; rh++) {
                const int row = wm * 32 + t * 16 + (l >> 2) + rh * 8;
#pragma unroll
                for (int nb = 0; nb < 16; nb++) {
                    const int col = nb * 8 + (l & 3) * 2;
                    float2 v = *(float2*)(obuf + row * 128 + col);
                    v.x += accO[t][nb][rh * 2 + 0];
                    v.y += accO[t][nb][rh * 2 + 1];
                    *(float2*)(obase + (size_t)row * Dd + col) = v;
                }
            }
    }
}

// ---------------- combine partials -> out ----------------
__global__ __launch_bounds__(256) void combine_kernel(float* __restrict__ outp)
{
    const size_t idx = (size_t)blockIdx.x * blockDim.x + threadIdx.x;
    const size_t e = idx * 4;
    const int m = (int)(e >> 12);
    const int c = (int)(e & (Nn - 1));
    const int h = c >> 7;
    const int d = c & 127;

    const size_t rbase = (size_t)h * Mq + m;
    const float tot = g_rs[rbase] + g_rs[(size_t)Hh * Mq + rbase]
                    + g_rs[2 * (size_t)Hh * Mq + rbase] + g_rs[3 * (size_t)Hh * Mq + rbase];
    const float inv = 1.0f / tot;

    const size_t pbase = ((size_t)h * Mq + m) * Dd + d;
    const size_t pstep = (size_t)Hh * Mq * Dd;
    float4 a = *(const float4*)(g_Opart + pbase);
    float4 b = *(const float4*)(g_Opart + pbase + pstep);
    float4 cc = *(const float4*)(g_Opart + pbase + 2 * pstep);
    float4 dd = *(const float4*)(g_Opart + pbase + 3 * pstep);
    float4 o;
    o.x = (a.x + b.x + cc.x + dd.x) * inv;
    o.y = (a.y + b.y + cc.y + dd.y) * inv;
    o.z = (a.z + b.z + cc.z + dd.z) * inv;
    o.w = (a.w + b.w + cc.w + dd.w) * inv;
    *(float4*)(outp + e) = o;
}

// ---------------- prep ----------------
__global__ __launch_bounds__(256) void convert_inputs(
    const float* __restrict__ X, const float* __restrict__ cK, const float* __restrict__ cV)
{
    const size_t stride = (size_t)gridDim.x * blockDim.x;
    const size_t tid0 = (size_t)blockIdx.x * blockDim.x + threadIdx.x;

    for (size_t i = tid0; i < (size_t)Mq * Nn; i += stride) {
        bf16 h, lo;
        split_bf16(X[i], h, lo);
        g_Xh[i] = h; g_Xl[i] = lo;
    }
    const size_t nkv = (size_t)Hh * Pp * Dd;
    for (size_t i = tid0; i < nkv; i += stride) {
        const size_t h = i / ((size_t)Pp * Dd);
        const size_t r = i % ((size_t)Pp * Dd);
        const size_t o = h * (size_t)NKEYS * Dd + r;
        bf16 hh, lo;
        split_bf16(cK[i], hh, lo);
        g_Kh[o] = hh; g_Kl[o] = lo;
        split_bf16(cV[i], hh, lo);
        g_Vh[o] = hh; g_Vl[o] = lo;
    }
}

// ---------------- host launcher ----------------
extern "C" void kernel_launch(void* const* d_in, const int* in_sizes, int n_in,
                              void* d_out, int out_size)
{
    const float* X  = (const float*)d_in[0];
    const float* Wq = (const float*)d_in[1];
    const float* Wk = (const float*)d_in[2];
    const float* Wv = (const float*)d_in[3];
    const float* cK = (const float*)d_in[4];
    const float* cV = (const float*)d_in[5];
    float* out = (float*)d_out;

    bf16 *xh, *xl;
    cudaGetSymbolAddress((void**)&xh, g_Xh);
    cudaGetSymbolAddress((void**)&xl, g_Xl);

    cudaFuncSetAttribute(proj_kernel, cudaFuncAttributeMaxDynamicSharedMemorySize, SMEM_PROJ);
    cudaFuncSetAttribute(attn_kernel, cudaFuncAttributeMaxDynamicSharedMemorySize, SMEM_ATT);

    convert_inputs<<<4096, 256>>>(X, cK, cV);

    proj_kernel<<<dim3(Nn / 128, Mq / 256, 3), 256, SMEM_PROJ>>>(xh, xl, Wq, Wk, Wv);

    attn_kernel<<<dim3(Mq / 128, Hh, NSPLIT), 256, SMEM_ATT>>>();

    combine_kernel<<<(Mq * Nn / 4) / 256, 256>>>(out);
}

// round 16
// speedup vs baseline: 1.0283x; 1.0103x over previous
#include <cuda_runtime.h>
#include <cuda_bf16.h>
#include <math.h>
#include <stdint.h>

#define Mq 1024
#define Nn 4096
#define Dd 128
#define Pp 3072
#define Hh 32
#define NKEYS 4096
#define NSPLIT 4
#define KEYB 64
#define NIT ((NKEYS / NSPLIT) / KEYB)   // 16
#define LOG2E 1.4426950408889634f
typedef __nv_bfloat16 bf16;

// ---------------- scratch ----------------
__device__ bf16 g_Xh[(size_t)Mq * Nn],       g_Xl[(size_t)Mq * Nn];
__device__ bf16 g_Qh[(size_t)Hh * Mq * Dd],  g_Ql[(size_t)Hh * Mq * Dd];
__device__ bf16 g_Kh[(size_t)Hh * NKEYS * Dd], g_Kl[(size_t)Hh * NKEYS * Dd];
__device__ bf16 g_Vh[(size_t)Hh * NKEYS * Dd], g_Vl[(size_t)Hh * NKEYS * Dd];
__device__ float g_Opart[(size_t)NSPLIT * Hh * Mq * Dd];
__device__ float g_rs[(size_t)NSPLIT * Hh * Mq];

// ---------------- helpers ----------------
static __device__ __forceinline__ uint32_t smem_u32(const void* p) {
    uint32_t a;
    asm("{ .reg .u64 t; cvta.to.shared.u64 t, %1; cvt.u32.u64 %0, t; }" : "=r"(a) : "l"(p));
    return a;
}
static __device__ __forceinline__ void cp_async16(uint32_t dst, const void* src) {
    asm volatile("cp.async.cg.shared.global [%0], [%1], 16;" :: "r"(dst), "l"(src));
}
#define CP_COMMIT() asm volatile("cp.async.commit_group;" ::: "memory")
#define CP_WAIT(n)  asm volatile("cp.async.wait_group %0;" :: "n"(n) : "memory")

static __device__ __forceinline__ void ldsm_x4(uint32_t& r0, uint32_t& r1, uint32_t& r2, uint32_t& r3,
                                               uint32_t addr) {
    asm volatile("ldmatrix.sync.aligned.m8n8.x4.shared.b16 {%0,%1,%2,%3}, [%4];"
                 : "=r"(r0), "=r"(r1), "=r"(r2), "=r"(r3) : "r"(addr));
}
static __device__ __forceinline__ void ldsm_x4_t(uint32_t& r0, uint32_t& r1, uint32_t& r2, uint32_t& r3,
                                                 uint32_t addr) {
    asm volatile("ldmatrix.sync.aligned.m8n8.x4.trans.shared.b16 {%0,%1,%2,%3}, [%4];"
                 : "=r"(r0), "=r"(r1), "=r"(r2), "=r"(r3) : "r"(addr));
}
static __device__ __forceinline__ void mma_bf16(float* c, const uint32_t* a, const uint32_t* b) {
    asm volatile(
        "mma.sync.aligned.m16n8k16.row.col.f32.bf16.bf16.f32 "
        "{%0,%1,%2,%3}, {%4,%5,%6,%7}, {%8,%9}, {%0,%1,%2,%3};"
        : "+f"(c[0]), "+f"(c[1]), "+f"(c[2]), "+f"(c[3])
        : "r"(a[0]), "r"(a[1]), "r"(a[2]), "r"(a[3]), "r"(b[0]), "r"(b[1]));
}
static __device__ __forceinline__ uint32_t cvt_bf16x2(float a, float b) {
    uint32_t r;
    asm("cvt.rn.bf16x2.f32 %0, %1, %2;" : "=r"(r) : "f"(b), "f"(a));
    return r;
}
static __device__ __forceinline__ void split_pair(float v0, float v1, uint32_t& ph, uint32_t& pl) {
    ph = cvt_bf16x2(v0, v1);
    const float h0 = __uint_as_float(ph << 16);
    const float h1 = __uint_as_float(ph & 0xFFFF0000u);
    pl = cvt_bf16x2(v0 - h0, v1 - h1);
}
static __device__ __forceinline__ float ex2(float x) {
    float r;
    asm("ex2.approx.f32 %0, %1;" : "=f"(r) : "f"(x));
    return r;
}

// proj smem: rbuf 2048 | X stages 2x64KB | Wsplit 2x32KB
#define PROJ_XS   (2048)
#define PROJ_WS   (2048 + 131072)
#define SMEM_PROJ (2048 + 131072 + 65536)
// attn: rbuf 2048 | Q 64K (reused as O-reduce buf) | K ring 2x32K | V ring 2x32K
#define SMEM_ATT  (2048 + 65536 + 65536 + 65536)

// ---------------- projection GEMM: TM=256, TN=128, 256 thr, interleaved W split ----------------
__global__ __launch_bounds__(256, 1) void proj_kernel(
    const bf16* __restrict__ Xh, const bf16* __restrict__ Xl,
    const float* __restrict__ Wq, const float* __restrict__ Wk, const float* __restrict__ Wv)
{
    extern __shared__ char smem[];
    float* rbuf = (float*)smem;
    const uint32_t sb = smem_u32(smem);
    const int tid = threadIdx.x;
    const int wid = tid >> 5, l = tid & 31;
    const int wm = wid >> 1, wn = wid & 1;
    const int bn = blockIdx.x * 128, bm = blockIdx.y * 256, z = blockIdx.z;

    const float* Wp = (z == 0) ? Wq : (z == 1) ? Wk : Wv;

    float acc[4][8][4];
#pragma unroll
    for (int t = 0; t < 4; t++)
#pragma unroll
        for (int nb = 0; nb < 8; nb++)
#pragma unroll
            for (int i = 0; i < 4; i++) acc[t][nb][i] = 0.f;

    const int nch = Nn >> 6;

    auto load_X = [&](int c) {
        const int k0 = c << 6;
        const uint32_t xb = sb + PROJ_XS + (c & 1) * 65536;
#pragma unroll
        for (int p = 0; p < 2; p++) {
            const bf16* src = p ? Xl : Xh;
#pragma unroll
            for (int i = tid; i < 2048; i += 256) {
                const int row = i >> 3, cc = i & 7;
                const uint32_t off = (uint32_t)(row * 128 + cc * 16);
                cp_async16(xb + p * 32768 + (off ^ (uint32_t)((row & 7) << 4)),
                           src + (size_t)(bm + row) * Nn + k0 + cc * 8);
            }
        }
        CP_COMMIT();
    };

    float4 w4[4], w4b[4];
    auto ldg_W8 = [&](int c) {
        const int k0 = c << 6;
#pragma unroll
        for (int j = 0; j < 4; j++) {
            const int i = tid + j * 256;
            w4[j] = __ldg((const float4*)(Wp + (size_t)(k0 + (i >> 5)) * Nn + bn + (i & 31) * 4));
        }
#pragma unroll
        for (int j = 0; j < 4; j++) {
            const int i = tid + (j + 4) * 256;
            w4b[j] = __ldg((const float4*)(Wp + (size_t)(k0 + (i >> 5)) * Nn + bn + (i & 31) * 4));
        }
    };
    auto sts_W = [&](int buf) {
        char* ws = smem + PROJ_WS + buf * 32768;
#pragma unroll
        for (int j = 0; j < 8; j++) {
            const int i = tid + j * 256;
            const int row = i >> 5, c16 = i & 31;
            const float4 w = (j < 4) ? w4[j] : w4b[j - 4];
            uint32_t h01, l01, h23, l23;
            split_pair(w.x, w.y, h01, l01);
            split_pair(w.z, w.w, h23, l23);
            const uint32_t off = (uint32_t)(row * 256 + c16 * 8);
            const uint32_t sw = off ^ (uint32_t)((row & 7) << 4);
            *(uint2*)(ws + sw) = make_uint2(h01, h23);
            *(uint2*)(ws + 16384 + sw) = make_uint2(l01, l23);
        }
    };

    ldg_W8(0);
    load_X(0);
    load_X(1);
    CP_WAIT(1);
    __syncthreads();
    sts_W(0);
    ldg_W8(1);
    __syncthreads();

    for (int c = 0; c < nch; c++) {
        const uint32_t xb = sb + PROJ_XS + (c & 1) * 65536;
        const uint32_t wsb = sb + PROJ_WS + (c & 1) * 32768;

        auto do_kk = [&](int kk) {
            uint32_t bH[8][2], bL[8][2];
#pragma unroll
            for (int bt = 0; bt < 4; bt++) {
                const int krow = kk * 16 + (l & 7) + ((l >> 3) & 1) * 8;
                const int colb = wn * 128 + bt * 32 + ((l >> 4) & 1) * 16;
                const uint32_t bo = (uint32_t)(krow * 256) + (uint32_t)(colb ^ ((krow & 7) << 4));
                ldsm_x4_t(bH[2 * bt][0], bH[2 * bt][1], bH[2 * bt + 1][0], bH[2 * bt + 1][1],
                          wsb + bo);
                ldsm_x4_t(bL[2 * bt][0], bL[2 * bt][1], bL[2 * bt + 1][0], bL[2 * bt + 1][1],
                          wsb + 16384 + bo);
            }
#pragma unroll
            for (int t = 0; t < 4; t++) {
                uint32_t aH[4], aL[4];
                const int mrow = wm * 64 + t * 16 + (l & 7) + ((l >> 3) & 1) * 8;
                const int kb = kk * 32 + ((l >> 4) & 1) * 16;
                const uint32_t ao = (uint32_t)(mrow * 128) + (uint32_t)(kb ^ ((mrow & 7) << 4));
                ldsm_x4(aH[0], aH[1], aH[2], aH[3], xb + ao);
                ldsm_x4(aL[0], aL[1], aL[2], aL[3], xb + 32768 + ao);
#pragma unroll
                for (int nb = 0; nb < 8; nb++) {
                    mma_bf16(acc[t][nb], aH, bH[nb]);
                    mma_bf16(acc[t][nb], aH, bL[nb]);
                    mma_bf16(acc[t][nb], aL, bH[nb]);
                }
            }
        };

        // kk=0 first so the W split/prefetch interleaves with MMA bubbles of kk 1-3
        do_kk(0);
        if (c + 1 < nch) {
            sts_W((c + 1) & 1);
            if (c + 2 < nch) ldg_W8(c + 2);
        }
        do_kk(1);
        do_kk(2);
        do_kk(3);

        if (c + 1 < nch) {
            __syncthreads();
            if (c + 2 < nch) load_X(c + 2); else CP_COMMIT();
            CP_WAIT(1);
            __syncthreads();
        }
    }

    __syncthreads();
    if (z < 2) {
        float ss[8];
#pragma unroll
        for (int s = 0; s < 8; s++) ss[s] = 0.f;
#pragma unroll
        for (int t = 0; t < 4; t++)
#pragma unroll
            for (int nb = 0; nb < 8; nb++)
#pragma unroll
                for (int i = 0; i < 4; i++) {
                    const float v = acc[t][nb][i];
                    ss[t * 2 + (i >> 1)] += v * v;
                }
#pragma unroll
        for (int s = 0; s < 8; s++) {
            ss[s] += __shfl_xor_sync(0xffffffffu, ss[s], 1);
            ss[s] += __shfl_xor_sync(0xffffffffu, ss[s], 2);
        }
        if ((l & 3) == 0) {
#pragma unroll
            for (int s = 0; s < 8; s++) {
                const int row = wm * 64 + (s >> 1) * 16 + (l >> 2) + (s & 1) * 8;
                rbuf[wn * 256 + row] = ss[s];
            }
        }
        __syncthreads();
    }

    bf16* dh = (z == 0) ? g_Qh : (z == 1) ? g_Kh : g_Vh;
    bf16* dl = (z == 0) ? g_Ql : (z == 1) ? g_Kl : g_Vl;
#pragma unroll
    for (int t = 0; t < 4; t++)
#pragma unroll
        for (int rh = 0; rh < 2; rh++) {
            const int row = wm * 64 + t * 16 + (l >> 2) + rh * 8;
            float sc = 1.0f;
            if (z < 2) sc = rsqrtf((rbuf[row] + rbuf[256 + row]) * (1.0f / 128.0f));
            if (z == 0) sc *= LOG2E;
            const size_t rowbase = (z == 0)
                ? ((size_t)blockIdx.x * Mq + bm + row) * 128
                : ((size_t)blockIdx.x * NKEYS + Pp + bm + row) * 128;
#pragma unroll
            for (int nb = 0; nb < 8; nb++) {
                const int col = wn * 64 + nb * 8 + (l & 3) * 2;
                uint32_t ph, pl;
                split_pair(acc[t][nb][rh * 2 + 0] * sc, acc[t][nb][rh * 2 + 1] * sc, ph, pl);
                *(uint32_t*)(dh + rowbase + col) = ph;
                *(uint32_t*)(dl + rowbase + col) = pl;
            }
        }
}

// ---------------- fused flash attention (R15, unchanged) ----------------
__global__ __launch_bounds__(256, 1) void attn_kernel()
{
    extern __shared__ char smem[];
    float* rbuf = (float*)smem;
    const uint32_t sb = smem_u32(smem);
    const uint32_t Qb = sb + 2048;
    const uint32_t Kr = Qb + 65536;
    const uint32_t Vr = Kr + 65536;

    const int tid = threadIdx.x;
    const int wid = tid >> 5, l = tid & 31;
    const int wm = wid >> 1, wn = wid & 1;
    const int bm = blockIdx.x * 128;
    const int z = blockIdx.y;
    const int sp = blockIdx.z;
    const int key0 = sp * (NKEYS / NSPLIT);

    const bf16* Qhp = g_Qh + ((size_t)z * Mq + bm) * Dd;
    const bf16* Qlp = g_Ql + ((size_t)z * Mq + bm) * Dd;
    const bf16* Khp = g_Kh + (size_t)z * NKEYS * Dd;
    const bf16* Klp = g_Kl + (size_t)z * NKEYS * Dd;
    const bf16* Vhp = g_Vh + (size_t)z * NKEYS * Dd;
    const bf16* Vlp = g_Vl + (size_t)z * NKEYS * Dd;

    auto load_Q = [&]() {
#pragma unroll
        for (int j = 0; j < 16; j++) {
            const int i = tid + j * 256;
            const int plane = i >> 10, row = (i >> 3) & 127, cc = i & 7;
            const bf16* src = (plane < 2) ? Qhp : Qlp;
            const int k0 = (plane & 1) * 64;
            const uint32_t off = (uint32_t)(row * 128 + cc * 16);
            cp_async16(Qb + plane * 16384 + (off ^ (uint32_t)((row & 7) << 4)),
                       src + (size_t)row * Dd + k0 + cc * 8);
        }
    };
    auto load_K = [&](int buf, int krow0) {
#pragma unroll
        for (int j = 0; j < 8; j++) {
            const int i = tid + j * 256;
            const int plane = i >> 9, row = (i >> 3) & 63, cc = i & 7;
            const bf16* src = (plane < 2) ? Khp : Klp;
            const int k0 = (plane & 1) * 64;
            const uint32_t off = (uint32_t)(row * 128 + cc * 16);
            cp_async16(Kr + buf * 32768 + plane * 8192 + (off ^ (uint32_t)((row & 7) << 4)),
                       src + (size_t)(krow0 + row) * Dd + k0 + cc * 8);
        }
    };
    auto load_V = [&](int buf, int krow0) {
#pragma unroll
        for (int j = 0; j < 8; j++) {
            const int i = tid + j * 256;
            const int plane = i >> 10, row = (i >> 4) & 63, c16 = i & 15;
            const bf16* src = plane ? Vlp : Vhp;
            const uint32_t off = (uint32_t)(row * 256 + c16 * 16);
            cp_async16(Vr + buf * 32768 + plane * 16384 + (off ^ (uint32_t)((row & 7) << 4)),
                       src + (size_t)(krow0 + row) * Dd + c16 * 8);
        }
    };

    auto do_mma_qk = [&](float acc[2][4][4], uint32_t kbuf) {
#pragma unroll
        for (int c = 0; c < 2; c++) {
            const uint32_t aHb = Qb + c * 16384, aLb = Qb + 32768 + c * 16384;
            const uint32_t bHb = kbuf + c * 8192, bLb = kbuf + 16384 + c * 8192;
#pragma unroll
            for (int kk = 0; kk < 4; kk++) {
                uint32_t aH[2][4], aL[2][4];
#pragma unroll
                for (int t = 0; t < 2; t++) {
                    const int mrow = wm * 32 + t * 16 + (l & 7) + ((l >> 3) & 1) * 8;
                    const int kb = kk * 32 + ((l >> 4) & 1) * 16;
                    const uint32_t ao = (uint32_t)(mrow * 128) + (uint32_t)(kb ^ ((mrow & 7) << 4));
                    ldsm_x4(aH[t][0], aH[t][1], aH[t][2], aH[t][3], aHb + ao);
                    ldsm_x4(aL[t][0], aL[t][1], aL[t][2], aL[t][3], aLb + ao);
                }
                uint32_t bH[4][2], bL[4][2];
#pragma unroll
                for (int bt = 0; bt < 2; bt++) {
                    const int nrow = wn * 32 + bt * 16 + (l & 7) + ((l >> 4) & 1) * 8;
                    const int kb = kk * 32 + ((l >> 3) & 1) * 16;
                    const uint32_t bo = (uint32_t)(nrow * 128) + (uint32_t)(kb ^ ((nrow & 7) << 4));
                    ldsm_x4(bH[2 * bt][0], bH[2 * bt][1], bH[2 * bt + 1][0], bH[2 * bt + 1][1], bHb + bo);
                    ldsm_x4(bL[2 * bt][0], bL[2 * bt][1], bL[2 * bt + 1][0], bL[2 * bt + 1][1], bLb + bo);
                }
#pragma unroll
                for (int t = 0; t < 2; t++)
#pragma unroll
                    for (int nb = 0; nb < 4; nb++) {
                        mma_bf16(acc[t][nb], aH[t], bH[nb]);
                        mma_bf16(acc[t][nb], aH[t], bL[nb]);
                        mma_bf16(acc[t][nb], aL[t], bH[nb]);
                    }
            }
        }
    };

    float accO[2][16][4];
#pragma unroll
    for (int t = 0; t < 2; t++)
#pragma unroll
        for (int nb = 0; nb < 16; nb++)
#pragma unroll
            for (int i = 0; i < 4; i++) accO[t][nb][i] = 0.f;
    float rs[4] = {0.f, 0.f, 0.f, 0.f};

    load_Q();
    load_K(0, key0);
    load_V(0, key0);
    CP_COMMIT();

    for (int it = 0; it < NIT; it++) {
        CP_WAIT(0);
        __syncthreads();

        if (it + 1 < NIT) {
            load_K((it + 1) & 1, key0 + (it + 1) * KEYB);
            load_V((it + 1) & 1, key0 + (it + 1) * KEYB);
        }
        CP_COMMIT();

        float accS[2][4][4];
#pragma unroll
        for (int t = 0; t < 2; t++)
#pragma unroll
            for (int nb = 0; nb < 4; nb++)
#pragma unroll
                for (int i = 0; i < 4; i++) accS[t][nb][i] = 0.f;

        do_mma_qk(accS, Kr + (it & 1) * 32768);

        const uint32_t vbuf = Vr + (it & 1) * 32768;
#pragma unroll
        for (int st = 0; st < 2; st++) {
            uint32_t aH[2][4], aL[2][4];
#pragma unroll
            for (int t = 0; t < 2; t++)
#pragma unroll
                for (int j = 0; j < 2; j++) {
                    const int nb = 2 * st + j;
#pragma unroll
                    for (int rh = 0; rh < 2; rh++) {
                        const float e0 = ex2(accS[t][nb][rh * 2 + 0]);
                        const float e1 = ex2(accS[t][nb][rh * 2 + 1]);
                        rs[t * 2 + rh] += e0 + e1;
                        split_pair(e0, e1, aH[t][j * 2 + rh], aL[t][j * 2 + rh]);
                    }
                }
            const int key = (wn * 2 + st) * 16 + (l & 7) + ((l >> 3) & 1) * 8;
#pragma unroll
            for (int bt = 0; bt < 8; bt++) {
                const int colb = bt * 32 + ((l >> 4) & 1) * 16;
                const uint32_t bo = (uint32_t)(key * 256) + (uint32_t)(colb ^ ((key & 7) << 4));
                uint32_t bH[2][2], bL[2][2];
                ldsm_x4_t(bH[0][0], bH[0][1], bH[1][0], bH[1][1], vbuf + bo);
                ldsm_x4_t(bL[0][0], bL[0][1], bL[1][0], bL[1][1], vbuf + 16384 + bo);
#pragma unroll
                for (int t = 0; t < 2; t++)
#pragma unroll
                    for (int j = 0; j < 2; j++) {
                        mma_bf16(accO[t][2 * bt + j], aH[t], bH[j]);
                        mma_bf16(accO[t][2 * bt + j], aH[t], bL[j]);
                        mma_bf16(accO[t][2 * bt + j], aL[t], bH[j]);
                    }
            }
        }
    }
    __syncthreads();

    float* obuf = (float*)(smem + 2048);

    if (wn == 1) {
#pragma unroll
        for (int t = 0; t < 2; t++)
#pragma unroll
            for (int rh = 0; rh < 2; rh++) {
                const int row = wm * 32 + t * 16 + (l >> 2) + rh * 8;
#pragma unroll
                for (int nb = 0; nb < 16; nb++) {
                    const int col = nb * 8 + (l & 3) * 2;
                    float2 v;
                    v.x = accO[t][nb][rh * 2 + 0];
                    v.y = accO[t][nb][rh * 2 + 1];
                    *(float2*)(obuf + row * 128 + col) = v;
                }
            }
    }

#pragma unroll
    for (int s = 0; s < 4; s++) {
        rs[s] += __shfl_xor_sync(0xffffffffu, rs[s], 1);
        rs[s] += __shfl_xor_sync(0xffffffffu, rs[s], 2);
    }
    __syncthreads();

    if ((l & 3) == 0) {
#pragma unroll
        for (int s = 0; s < 4; s++) {
            const int row = wm * 32 + (s >> 1) * 16 + (l >> 2) + (s & 1) * 8;
            rbuf[wn * 128 + row] = rs[s];
        }
    }
    __syncthreads();

    if (tid < 128) {
        g_rs[((size_t)sp * Hh + z) * Mq + bm + tid] = rbuf[tid] + rbuf[128 + tid];
    }

    if (wn == 0) {
        float* obase = g_Opart + (((size_t)sp * Hh + z) * Mq + bm) * Dd;
#pragma unroll
        for (int t = 0; t < 2; t++)
#pragma unroll
            for (int rh = 0; rh < 2; rh++) {
                const int row = wm * 32 + t * 16 + (l >> 2) + rh * 8;
#pragma unroll
                for (int nb = 0; nb < 16; nb++) {
                    const int col = nb * 8 + (l & 3) * 2;
                    float2 v = *(float2*)(obuf + row * 128 + col);
                    v.x += accO[t][nb][rh * 2 + 0];
                    v.y += accO[t][nb][rh * 2 + 1];
                    *(float2*)(obase + (size_t)row * Dd + col) = v;
                }
            }
    }
}

// ---------------- combine partials -> out ----------------
__global__ __launch_bounds__(256) void combine_kernel(float* __restrict__ outp)
{
    const size_t idx = (size_t)blockIdx.x * blockDim.x + threadIdx.x;
    const size_t e = idx * 4;
    const int m = (int)(e >> 12);
    const int c = (int)(e & (Nn - 1));
    const int h = c >> 7;
    const int d = c & 127;

    const size_t rbase = (size_t)h * Mq + m;
    const float tot = g_rs[rbase] + g_rs[(size_t)Hh * Mq + rbase]
                    + g_rs[2 * (size_t)Hh * Mq + rbase] + g_rs[3 * (size_t)Hh * Mq + rbase];
    const float inv = 1.0f / tot;

    const size_t pbase = ((size_t)h * Mq + m) * Dd + d;
    const size_t pstep = (size_t)Hh * Mq * Dd;
    float4 a = *(const float4*)(g_Opart + pbase);
    float4 b = *(const float4*)(g_Opart + pbase + pstep);
    float4 cc = *(const float4*)(g_Opart + pbase + 2 * pstep);
    float4 dd = *(const float4*)(g_Opart + pbase + 3 * pstep);
    float4 o;
    o.x = (a.x + b.x + cc.x + dd.x) * inv;
    o.y = (a.y + b.y + cc.y + dd.y) * inv;
    o.z = (a.z + b.z + cc.z + dd.z) * inv;
    o.w = (a.w + b.w + cc.w + dd.w) * inv;
    *(float4*)(outp + e) = o;
}

// ---------------- prep: float4-vectorized split-convert ----------------
static __device__ __forceinline__ void split4_store(const float4 v, bf16* dh, bf16* dl, size_t o) {
    uint32_t h01, l01, h23, l23;
    split_pair(v.x, v.y, h01, l01);
    split_pair(v.z, v.w, h23, l23);
    *(uint2*)(dh + o) = make_uint2(h01, h23);
    *(uint2*)(dl + o) = make_uint2(l01, l23);
}

__global__ __launch_bounds__(256) void convert_inputs(
    const float* __restrict__ X, const float* __restrict__ cK, const float* __restrict__ cV)
{
    const size_t stride = (size_t)gridDim.x * blockDim.x;
    const size_t tid0 = (size_t)blockIdx.x * blockDim.x + threadIdx.x;

    const size_t nx4 = (size_t)Mq * Nn / 4;
    for (size_t i = tid0; i < nx4; i += stride) {
        split4_store(*(const float4*)(X + i * 4), g_Xh, g_Xl, i * 4);
    }
    const size_t nkv4 = (size_t)Hh * Pp * Dd / 4;
    const size_t perh4 = (size_t)Pp * Dd / 4;   // 98304
    for (size_t i = tid0; i < nkv4; i += stride) {
        const size_t h = i / perh4;
        const size_t r = i - h * perh4;
        const size_t o = (h * (size_t)NKEYS * Dd) + r * 4;
        split4_store(*(const float4*)(cK + i * 4), g_Kh, g_Kl, o);
        split4_store(*(const float4*)(cV + i * 4), g_Vh, g_Vl, o);
    }
}

// ---------------- host launcher ----------------
extern "C" void kernel_launch(void* const* d_in, const int* in_sizes, int n_in,
                              void* d_out, int out_size)
{
    const float* X  = (const float*)d_in[0];
    const float* Wq = (const float*)d_in[1];
    const float* Wk = (const float*)d_in[2];
    const float* Wv = (const float*)d_in[3];
    const float* cK = (const float*)d_in[4];
    const float* cV = (const float*)d_in[5];
    float* out = (float*)d_out;

    bf16 *xh, *xl;
    cudaGetSymbolAddress((void**)&xh, g_Xh);
    cudaGetSymbolAddress((void**)&xl, g_Xl);

    cudaFuncSetAttribute(proj_kernel, cudaFuncAttributeMaxDynamicSharedMemorySize, SMEM_PROJ);
    cudaFuncSetAttribute(attn_kernel, cudaFuncAttributeMaxDynamicSharedMemorySize, SMEM_ATT);

    convert_inputs<<<2048, 256>>>(X, cK, cV);

    proj_kernel<<<dim3(Nn / 128, Mq / 256, 3), 256, SMEM_PROJ>>>(xh, xl, Wq, Wk, Wv);

    attn_kernel<<<dim3(Mq / 128, Hh, NSPLIT), 256, SMEM_ATT>>>();

    combine_kernel<<<(Mq * Nn / 4) / 256, 256>>>(out);
}

// round 17
// speedup vs baseline: 1.0634x; 1.0342x over previous
#include <cuda_runtime.h>
#include <cuda_bf16.h>
#include <math.h>
#include <stdint.h>

#define Mq 1024
#define Nn 4096
#define Dd 128
#define Pp 3072
#define Hh 32
#define NKEYS 4096
#define NSPLIT 4
#define KEYB 64
#define NIT ((NKEYS / NSPLIT) / KEYB)   // 16
#define LOG2E 1.4426950408889634f
typedef __nv_bfloat16 bf16;

// ---------------- scratch ----------------
__device__ bf16 g_Xh[(size_t)Mq * Nn],       g_Xl[(size_t)Mq * Nn];
__device__ bf16 g_Qh[(size_t)Hh * Mq * Dd],  g_Ql[(size_t)Hh * Mq * Dd];
__device__ bf16 g_Kh[(size_t)Hh * NKEYS * Dd], g_Kl[(size_t)Hh * NKEYS * Dd];
__device__ bf16 g_Vh[(size_t)Hh * NKEYS * Dd], g_Vl[(size_t)Hh * NKEYS * Dd];
__device__ float g_Opart[(size_t)NSPLIT * Hh * Mq * Dd];
__device__ float g_rs[(size_t)NSPLIT * Hh * Mq];

// ---------------- helpers ----------------
static __device__ __forceinline__ uint32_t smem_u32(const void* p) {
    uint32_t a;
    asm("{ .reg .u64 t; cvta.to.shared.u64 t, %1; cvt.u32.u64 %0, t; }" : "=r"(a) : "l"(p));
    return a;
}
static __device__ __forceinline__ void cp_async16(uint32_t dst, const void* src) {
    asm volatile("cp.async.cg.shared.global [%0], [%1], 16;" :: "r"(dst), "l"(src));
}
#define CP_COMMIT() asm volatile("cp.async.commit_group;" ::: "memory")
#define CP_WAIT(n)  asm volatile("cp.async.wait_group %0;" :: "n"(n) : "memory")

static __device__ __forceinline__ void ldsm_x4(uint32_t& r0, uint32_t& r1, uint32_t& r2, uint32_t& r3,
                                               uint32_t addr) {
    asm volatile("ldmatrix.sync.aligned.m8n8.x4.shared.b16 {%0,%1,%2,%3}, [%4];"
                 : "=r"(r0), "=r"(r1), "=r"(r2), "=r"(r3) : "r"(addr));
}
static __device__ __forceinline__ void ldsm_x4_t(uint32_t& r0, uint32_t& r1, uint32_t& r2, uint32_t& r3,
                                                 uint32_t addr) {
    asm volatile("ldmatrix.sync.aligned.m8n8.x4.trans.shared.b16 {%0,%1,%2,%3}, [%4];"
                 : "=r"(r0), "=r"(r1), "=r"(r2), "=r"(r3) : "r"(addr));
}
static __device__ __forceinline__ void mma_bf16(float* c, const uint32_t* a, const uint32_t* b) {
    asm volatile(
        "mma.sync.aligned.m16n8k16.row.col.f32.bf16.bf16.f32 "
        "{%0,%1,%2,%3}, {%4,%5,%6,%7}, {%8,%9}, {%0,%1,%2,%3};"
        : "+f"(c[0]), "+f"(c[1]), "+f"(c[2]), "+f"(c[3])
        : "r"(a[0]), "r"(a[1]), "r"(a[2]), "r"(a[3]), "r"(b[0]), "r"(b[1]));
}
static __device__ __forceinline__ uint32_t cvt_bf16x2(float a, float b) {
    uint32_t r;
    asm("cvt.rn.bf16x2.f32 %0, %1, %2;" : "=r"(r) : "f"(b), "f"(a));
    return r;
}
static __device__ __forceinline__ void split_pair(float v0, float v1, uint32_t& ph, uint32_t& pl) {
    ph = cvt_bf16x2(v0, v1);
    const float h0 = __uint_as_float(ph << 16);
    const float h1 = __uint_as_float(ph & 0xFFFF0000u);
    pl = cvt_bf16x2(v0 - h0, v1 - h1);
}
static __device__ __forceinline__ float ex2(float x) {
    float r;
    asm("ex2.approx.f32 %0, %1;" : "=f"(r) : "f"(x));
    return r;
}
static __device__ __forceinline__ void split4_store(const float4 v, bf16* dh, bf16* dl, size_t o) {
    uint32_t h01, l01, h23, l23;
    split_pair(v.x, v.y, h01, l01);
    split_pair(v.z, v.w, h23, l23);
    *(uint2*)(dh + o) = make_uint2(h01, h23);
    *(uint2*)(dl + o) = make_uint2(l01, l23);
}

// proj smem: rbuf 2048 | X stages 2x64KB | Wsplit 2x32KB
#define PROJ_XS   (2048)
#define PROJ_WS   (2048 + 131072)
#define SMEM_PROJ (2048 + 131072 + 65536)
// attn: rbuf 2048 | Q 64K (reused as O-reduce buf) | K ring 2x32K | V ring 2x32K
#define SMEM_ATT  (2048 + 65536 + 65536 + 65536)

// ---------------- projection GEMM + KV-convert backfill (z==3) ----------------
__global__ __launch_bounds__(256, 1) void proj_kernel(
    const bf16* __restrict__ Xh, const bf16* __restrict__ Xl,
    const float* __restrict__ Wq, const float* __restrict__ Wk, const float* __restrict__ Wv,
    const float* __restrict__ cK, const float* __restrict__ cV)
{
    extern __shared__ char smem[];
    float* rbuf = (float*)smem;
    const uint32_t sb = smem_u32(smem);
    const int tid = threadIdx.x;
    const int z = blockIdx.z;

    if (z == 3) {
        // KV split-convert backfill: 128 CTAs x 256 threads, float4-vectorized
        const int cta = blockIdx.y * 32 + blockIdx.x;        // 0..127
        const size_t nkv4 = (size_t)Hh * Pp * Dd / 4;        // 3,145,728
        const size_t per = nkv4 / 128;                       // 24576
        const size_t i0 = (size_t)cta * per;
        const size_t perh4 = (size_t)Pp * Dd / 4;            // 98304
        for (size_t i = i0 + tid; i < i0 + per; i += 256) {
            const size_t h = i / perh4;
            const size_t r = i - h * perh4;
            const size_t o = h * (size_t)NKEYS * Dd + r * 4;
            split4_store(*(const float4*)(cK + i * 4), g_Kh, g_Kl, o);
            split4_store(*(const float4*)(cV + i * 4), g_Vh, g_Vl, o);
        }
        return;
    }

    const int wid = tid >> 5, l = tid & 31;
    const int wm = wid >> 1, wn = wid & 1;
    const int bn = blockIdx.x * 128, bm = blockIdx.y * 256;

    const float* Wp = (z == 0) ? Wq : (z == 1) ? Wk : Wv;

    float acc[4][8][4];
#pragma unroll
    for (int t = 0; t < 4; t++)
#pragma unroll
        for (int nb = 0; nb < 8; nb++)
#pragma unroll
            for (int i = 0; i < 4; i++) acc[t][nb][i] = 0.f;

    const int nch = Nn >> 6;

    auto load_X = [&](int c) {
        const int k0 = c << 6;
        const uint32_t xb = sb + PROJ_XS + (c & 1) * 65536;
#pragma unroll
        for (int p = 0; p < 2; p++) {
            const bf16* src = p ? Xl : Xh;
#pragma unroll
            for (int i = tid; i < 2048; i += 256) {
                const int row = i >> 3, cc = i & 7;
                const uint32_t off = (uint32_t)(row * 128 + cc * 16);
                cp_async16(xb + p * 32768 + (off ^ (uint32_t)((row & 7) << 4)),
                           src + (size_t)(bm + row) * Nn + k0 + cc * 8);
            }
        }
        CP_COMMIT();
    };

    float4 w4[4], w4b[4];
    auto ldg_W8 = [&](int c) {
        const int k0 = c << 6;
#pragma unroll
        for (int j = 0; j < 4; j++) {
            const int i = tid + j * 256;
            w4[j] = __ldg((const float4*)(Wp + (size_t)(k0 + (i >> 5)) * Nn + bn + (i & 31) * 4));
        }
#pragma unroll
        for (int j = 0; j < 4; j++) {
            const int i = tid + (j + 4) * 256;
            w4b[j] = __ldg((const float4*)(Wp + (size_t)(k0 + (i >> 5)) * Nn + bn + (i & 31) * 4));
        }
    };
    auto sts_W = [&](int buf) {
        char* ws = smem + PROJ_WS + buf * 32768;
#pragma unroll
        for (int j = 0; j < 8; j++) {
            const int i = tid + j * 256;
            const int row = i >> 5, c16 = i & 31;
            const float4 w = (j < 4) ? w4[j] : w4b[j - 4];
            uint32_t h01, l01, h23, l23;
            split_pair(w.x, w.y, h01, l01);
            split_pair(w.z, w.w, h23, l23);
            const uint32_t off = (uint32_t)(row * 256 + c16 * 8);
            const uint32_t sw = off ^ (uint32_t)((row & 7) << 4);
            *(uint2*)(ws + sw) = make_uint2(h01, h23);
            *(uint2*)(ws + 16384 + sw) = make_uint2(l01, l23);
        }
    };

    ldg_W8(0);
    load_X(0);
    load_X(1);
    CP_WAIT(1);
    __syncthreads();
    sts_W(0);
    ldg_W8(1);
    __syncthreads();

    for (int c = 0; c < nch; c++) {
        const uint32_t xb = sb + PROJ_XS + (c & 1) * 65536;
        const uint32_t wsb = sb + PROJ_WS + (c & 1) * 32768;

        auto do_kk = [&](int kk) {
            uint32_t bH[8][2], bL[8][2];
#pragma unroll
            for (int bt = 0; bt < 4; bt++) {
                const int krow = kk * 16 + (l & 7) + ((l >> 3) & 1) * 8;
                const int colb = wn * 128 + bt * 32 + ((l >> 4) & 1) * 16;
                const uint32_t bo = (uint32_t)(krow * 256) + (uint32_t)(colb ^ ((krow & 7) << 4));
                ldsm_x4_t(bH[2 * bt][0], bH[2 * bt][1], bH[2 * bt + 1][0], bH[2 * bt + 1][1],
                          wsb + bo);
                ldsm_x4_t(bL[2 * bt][0], bL[2 * bt][1], bL[2 * bt + 1][0], bL[2 * bt + 1][1],
                          wsb + 16384 + bo);
            }
#pragma unroll
            for (int t = 0; t < 4; t++) {
                uint32_t aH[4], aL[4];
                const int mrow = wm * 64 + t * 16 + (l & 7) + ((l >> 3) & 1) * 8;
                const int kb = kk * 32 + ((l >> 4) & 1) * 16;
                const uint32_t ao = (uint32_t)(mrow * 128) + (uint32_t)(kb ^ ((mrow & 7) << 4));
                ldsm_x4(aH[0], aH[1], aH[2], aH[3], xb + ao);
                ldsm_x4(aL[0], aL[1], aL[2], aL[3], xb + 32768 + ao);
#pragma unroll
                for (int nb = 0; nb < 8; nb++) {
                    mma_bf16(acc[t][nb], aH, bH[nb]);
                    mma_bf16(acc[t][nb], aH, bL[nb]);
                    mma_bf16(acc[t][nb], aL, bH[nb]);
                }
            }
        };

        do_kk(0);
        if (c + 1 < nch) {
            sts_W((c + 1) & 1);
            if (c + 2 < nch) ldg_W8(c + 2);
        }
        do_kk(1);
        do_kk(2);
        do_kk(3);

        if (c + 1 < nch) {
            __syncthreads();
            if (c + 2 < nch) load_X(c + 2); else CP_COMMIT();
            CP_WAIT(1);
            __syncthreads();
        }
    }

    __syncthreads();
    if (z < 2) {
        float ss[8];
#pragma unroll
        for (int s = 0; s < 8; s++) ss[s] = 0.f;
#pragma unroll
        for (int t = 0; t < 4; t++)
#pragma unroll
            for (int nb = 0; nb < 8; nb++)
#pragma unroll
                for (int i = 0; i < 4; i++) {
                    const float v = acc[t][nb][i];
                    ss[t * 2 + (i >> 1)] += v * v;
                }
#pragma unroll
        for (int s = 0; s < 8; s++) {
            ss[s] += __shfl_xor_sync(0xffffffffu, ss[s], 1);
            ss[s] += __shfl_xor_sync(0xffffffffu, ss[s], 2);
        }
        if ((l & 3) == 0) {
#pragma unroll
            for (int s = 0; s < 8; s++) {
                const int row = wm * 64 + (s >> 1) * 16 + (l >> 2) + (s & 1) * 8;
                rbuf[wn * 256 + row] = ss[s];
            }
        }
        __syncthreads();
    }

    bf16* dh = (z == 0) ? g_Qh : (z == 1) ? g_Kh : g_Vh;
    bf16* dl = (z == 0) ? g_Ql : (z == 1) ? g_Kl : g_Vl;
#pragma unroll
    for (int t = 0; t < 4; t++)
#pragma unroll
        for (int rh = 0; rh < 2; rh++) {
            const int row = wm * 64 + t * 16 + (l >> 2) + rh * 8;
            float sc = 1.0f;
            if (z < 2) sc = rsqrtf((rbuf[row] + rbuf[256 + row]) * (1.0f / 128.0f));
            if (z == 0) sc *= LOG2E;
            const size_t rowbase = (z == 0)
                ? ((size_t)blockIdx.x * Mq + bm + row) * 128
                : ((size_t)blockIdx.x * NKEYS + Pp + bm + row) * 128;
#pragma unroll
            for (int nb = 0; nb < 8; nb++) {
                const int col = wn * 64 + nb * 8 + (l & 3) * 2;
                uint32_t ph, pl;
                split_pair(acc[t][nb][rh * 2 + 0] * sc, acc[t][nb][rh * 2 + 1] * sc, ph, pl);
                *(uint32_t*)(dh + rowbase + col) = ph;
                *(uint32_t*)(dl + rowbase + col) = pl;
            }
        }
}

// ---------------- fused flash attention (R15/R16, unchanged) ----------------
__global__ __launch_bounds__(256, 1) void attn_kernel()
{
    extern __shared__ char smem[];
    float* rbuf = (float*)smem;
    const uint32_t sb = smem_u32(smem);
    const uint32_t Qb = sb + 2048;
    const uint32_t Kr = Qb + 65536;
    const uint32_t Vr = Kr + 65536;

    const int tid = threadIdx.x;
    const int wid = tid >> 5, l = tid & 31;
    const int wm = wid >> 1, wn = wid & 1;
    const int bm = blockIdx.x * 128;
    const int z = blockIdx.y;
    const int sp = blockIdx.z;
    const int key0 = sp * (NKEYS / NSPLIT);

    const bf16* Qhp = g_Qh + ((size_t)z * Mq + bm) * Dd;
    const bf16* Qlp = g_Ql + ((size_t)z * Mq + bm) * Dd;
    const bf16* Khp = g_Kh + (size_t)z * NKEYS * Dd;
    const bf16* Klp = g_Kl + (size_t)z * NKEYS * Dd;
    const bf16* Vhp = g_Vh + (size_t)z * NKEYS * Dd;
    const bf16* Vlp = g_Vl + (size_t)z * NKEYS * Dd;

    auto load_Q = [&]() {
#pragma unroll
        for (int j = 0; j < 16; j++) {
            const int i = tid + j * 256;
            const int plane = i >> 10, row = (i >> 3) & 127, cc = i & 7;
            const bf16* src = (plane < 2) ? Qhp : Qlp;
            const int k0 = (plane & 1) * 64;
            const uint32_t off = (uint32_t)(row * 128 + cc * 16);
            cp_async16(Qb + plane * 16384 + (off ^ (uint32_t)((row & 7) << 4)),
                       src + (size_t)row * Dd + k0 + cc * 8);
        }
    };
    auto load_K = [&](int buf, int krow0) {
#pragma unroll
        for (int j = 0; j < 8; j++) {
            const int i = tid + j * 256;
            const int plane = i >> 9, row = (i >> 3) & 63, cc = i & 7;
            const bf16* src = (plane < 2) ? Khp : Klp;
            const int k0 = (plane & 1) * 64;
            const uint32_t off = (uint32_t)(row * 128 + cc * 16);
            cp_async16(Kr + buf * 32768 + plane * 8192 + (off ^ (uint32_t)((row & 7) << 4)),
                       src + (size_t)(krow0 + row) * Dd + k0 + cc * 8);
        }
    };
    auto load_V = [&](int buf, int krow0) {
#pragma unroll
        for (int j = 0; j < 8; j++) {
            const int i = tid + j * 256;
            const int plane = i >> 10, row = (i >> 4) & 63, c16 = i & 15;
            const bf16* src = plane ? Vlp : Vhp;
            const uint32_t off = (uint32_t)(row * 256 + c16 * 16);
            cp_async16(Vr + buf * 32768 + plane * 16384 + (off ^ (uint32_t)((row & 7) << 4)),
                       src + (size_t)(krow0 + row) * Dd + c16 * 8);
        }
    };

    auto do_mma_qk = [&](float acc[2][4][4], uint32_t kbuf) {
#pragma unroll
        for (int c = 0; c < 2; c++) {
            const uint32_t aHb = Qb + c * 16384, aLb = Qb + 32768 + c * 16384;
            const uint32_t bHb = kbuf + c * 8192, bLb = kbuf + 16384 + c * 8192;
#pragma unroll
            for (int kk = 0; kk < 4; kk++) {
                uint32_t aH[2][4], aL[2][4];
#pragma unroll
                for (int t = 0; t < 2; t++) {
                    const int mrow = wm * 32 + t * 16 + (l & 7) + ((l >> 3) & 1) * 8;
                    const int kb = kk * 32 + ((l >> 4) & 1) * 16;
                    const uint32_t ao = (uint32_t)(mrow * 128) + (uint32_t)(kb ^ ((mrow & 7) << 4));
                    ldsm_x4(aH[t][0], aH[t][1], aH[t][2], aH[t][3], aHb + ao);
                    ldsm_x4(aL[t][0], aL[t][1], aL[t][2], aL[t][3], aLb + ao);
                }
                uint32_t bH[4][2], bL[4][2];
#pragma unroll
                for (int bt = 0; bt < 2; bt++) {
                    const int nrow = wn * 32 + bt * 16 + (l & 7) + ((l >> 4) & 1) * 8;
                    const int kb = kk * 32 + ((l >> 3) & 1) * 16;
                    const uint32_t bo = (uint32_t)(nrow * 128) + (uint32_t)(kb ^ ((nrow & 7) << 4));
                    ldsm_x4(bH[2 * bt][0], bH[2 * bt][1], bH[2 * bt + 1][0], bH[2 * bt + 1][1], bHb + bo);
                    ldsm_x4(bL[2 * bt][0], bL[2 * bt][1], bL[2 * bt + 1][0], bL[2 * bt + 1][1], bLb + bo);
                }
#pragma unroll
                for (int t = 0; t < 2; t++)
#pragma unroll
                    for (int nb = 0; nb < 4; nb++) {
                        mma_bf16(acc[t][nb], aH[t], bH[nb]);
                        mma_bf16(acc[t][nb], aH[t], bL[nb]);
                        mma_bf16(acc[t][nb], aL[t], bH[nb]);
                    }
            }
        }
    };

    float accO[2][16][4];
#pragma unroll
    for (int t = 0; t < 2; t++)
#pragma unroll
        for (int nb = 0; nb < 16; nb++)
#pragma unroll
            for (int i = 0; i < 4; i++) accO[t][nb][i] = 0.f;
    float rs[4] = {0.f, 0.f, 0.f, 0.f};

    load_Q();
    load_K(0, key0);
    load_V(0, key0);
    CP_COMMIT();

    for (int it = 0; it < NIT; it++) {
        CP_WAIT(0);
        __syncthreads();

        if (it + 1 < NIT) {
            load_K((it + 1) & 1, key0 + (it + 1) * KEYB);
            load_V((it + 1) & 1, key0 + (it + 1) * KEYB);
        }
        CP_COMMIT();

        float accS[2][4][4];
#pragma unroll
        for (int t = 0; t < 2; t++)
#pragma unroll
            for (int nb = 0; nb < 4; nb++)
#pragma unroll
                for (int i = 0; i < 4; i++) accS[t][nb][i] = 0.f;

        do_mma_qk(accS, Kr + (it & 1) * 32768);

        const uint32_t vbuf = Vr + (it & 1) * 32768;
#pragma unroll
        for (int st = 0; st < 2; st++) {
            uint32_t aH[2][4], aL[2][4];
#pragma unroll
            for (int t = 0; t < 2; t++)
#pragma unroll
                for (int j = 0; j < 2; j++) {
                    const int nb = 2 * st + j;
#pragma unroll
                    for (int rh = 0; rh < 2; rh++) {
                        const float e0 = ex2(accS[t][nb][rh * 2 + 0]);
                        const float e1 = ex2(accS[t][nb][rh * 2 + 1]);
                        rs[t * 2 + rh] += e0 + e1;
                        split_pair(e0, e1, aH[t][j * 2 + rh], aL[t][j * 2 + rh]);
                    }
                }
            const int key = (wn * 2 + st) * 16 + (l & 7) + ((l >> 3) & 1) * 8;
#pragma unroll
            for (int bt = 0; bt < 8; bt++) {
                const int colb = bt * 32 + ((l >> 4) & 1) * 16;
                const uint32_t bo = (uint32_t)(key * 256) + (uint32_t)(colb ^ ((key & 7) << 4));
                uint32_t bH[2][2], bL[2][2];
                ldsm_x4_t(bH[0][0], bH[0][1], bH[1][0], bH[1][1], vbuf + bo);
                ldsm_x4_t(bL[0][0], bL[0][1], bL[1][0], bL[1][1], vbuf + 16384 + bo);
#pragma unroll
                for (int t = 0; t < 2; t++)
#pragma unroll
                    for (int j = 0; j < 2; j++) {
                        mma_bf16(accO[t][2 * bt + j], aH[t], bH[j]);
                        mma_bf16(accO[t][2 * bt + j], aH[t], bL[j]);
                        mma_bf16(accO[t][2 * bt + j], aL[t], bH[j]);
                    }
            }
        }
    }
    __syncthreads();

    float* obuf = (float*)(smem + 2048);

    if (wn == 1) {
#pragma unroll
        for (int t = 0; t < 2; t++)
#pragma unroll
            for (int rh = 0; rh < 2; rh++) {
                const int row = wm * 32 + t * 16 + (l >> 2) + rh * 8;
#pragma unroll
                for (int nb = 0; nb < 16; nb++) {
                    const int col = nb * 8 + (l & 3) * 2;
                    float2 v;
                    v.x = accO[t][nb][rh * 2 + 0];
                    v.y = accO[t][nb][rh * 2 + 1];
                    *(float2*)(obuf + row * 128 + col) = v;
                }
            }
    }

#pragma unroll
    for (int s = 0; s < 4; s++) {
        rs[s] += __shfl_xor_sync(0xffffffffu, rs[s], 1);
        rs[s] += __shfl_xor_sync(0xffffffffu, rs[s], 2);
    }
    __syncthreads();

    if ((l & 3) == 0) {
#pragma unroll
        for (int s = 0; s < 4; s++) {
            const int row = wm * 32 + (s >> 1) * 16 + (l >> 2) + (s & 1) * 8;
            rbuf[wn * 128 + row] = rs[s];
        }
    }
    __syncthreads();

    if (tid < 128) {
        g_rs[((size_t)sp * Hh + z) * Mq + bm + tid] = rbuf[tid] + rbuf[128 + tid];
    }

    if (wn == 0) {
        float* obase = g_Opart + (((size_t)sp * Hh + z) * Mq + bm) * Dd;
#pragma unroll
        for (int t = 0; t < 2; t++)
#pragma unroll
            for (int rh = 0; rh < 2; rh++) {
                const int row = wm * 32 + t * 16 + (l >> 2) + rh * 8;
#pragma unroll
                for (int nb = 0; nb < 16; nb++) {
                    const int col = nb * 8 + (l & 3) * 2;
                    float2 v = *(float2*)(obuf + row * 128 + col);
                    v.x += accO[t][nb][rh * 2 + 0];
                    v.y += accO[t][nb][rh * 2 + 1];
                    *(float2*)(obase + (size_t)row * Dd + col) = v;
                }
            }
    }
}

// ---------------- combine partials -> out ----------------
__global__ __launch_bounds__(256) void combine_kernel(float* __restrict__ outp)
{
    const size_t idx = (size_t)blockIdx.x * blockDim.x + threadIdx.x;
    const size_t e = idx * 4;
    const int m = (int)(e >> 12);
    const int c = (int)(e & (Nn - 1));
    const int h = c >> 7;
    const int d = c & 127;

    const size_t rbase = (size_t)h * Mq + m;
    const float tot = g_rs[rbase] + g_rs[(size_t)Hh * Mq + rbase]
                    + g_rs[2 * (size_t)Hh * Mq + rbase] + g_rs[3 * (size_t)Hh * Mq + rbase];
    const float inv = 1.0f / tot;

    const size_t pbase = ((size_t)h * Mq + m) * Dd + d;
    const size_t pstep = (size_t)Hh * Mq * Dd;
    float4 a = *(const float4*)(g_Opart + pbase);
    float4 b = *(const float4*)(g_Opart + pbase + pstep);
    float4 cc = *(const float4*)(g_Opart + pbase + 2 * pstep);
    float4 dd = *(const float4*)(g_Opart + pbase + 3 * pstep);
    float4 o;
    o.x = (a.x + b.x + cc.x + dd.x) * inv;
    o.y = (a.y + b.y + cc.y + dd.y) * inv;
    o.z = (a.z + b.z + cc.z + dd.z) * inv;
    o.w = (a.w + b.w + cc.w + dd.w) * inv;
    *(float4*)(outp + e) = o;
}

// ---------------- prep: X only (proj dependency) ----------------
__global__ __launch_bounds__(256) void convert_X(const float* __restrict__ X)
{
    const size_t stride = (size_t)gridDim.x * blockDim.x;
    const size_t nx4 = (size_t)Mq * Nn / 4;
    for (size_t i = (size_t)blockIdx.x * blockDim.x + threadIdx.x; i < nx4; i += stride) {
        split4_store(*(const float4*)(X + i * 4), g_Xh, g_Xl, i * 4);
    }
}

// ---------------- host launcher ----------------
extern "C" void kernel_launch(void* const* d_in, const int* in_sizes, int n_in,
                              void* d_out, int out_size)
{
    const float* X  = (const float*)d_in[0];
    const float* Wq = (const float*)d_in[1];
    const float* Wk = (const float*)d_in[2];
    const float* Wv = (const float*)d_in[3];
    const float* cK = (const float*)d_in[4];
    const float* cV = (const float*)d_in[5];
    float* out = (float*)d_out;

    bf16 *xh, *xl;
    cudaGetSymbolAddress((void**)&xh, g_Xh);
    cudaGetSymbolAddress((void**)&xl, g_Xl);

    cudaFuncSetAttribute(proj_kernel, cudaFuncAttributeMaxDynamicSharedMemorySize, SMEM_PROJ);
    cudaFuncSetAttribute(attn_kernel, cudaFuncAttributeMaxDynamicSharedMemorySize, SMEM_ATT);

    convert_X<<<1024, 256>>>(X);

    // z = 0..2: Q/K/V projections; z = 3: KV-cache split-convert backfill
    proj_kernel<<<dim3(Nn / 128, Mq / 256, 4), 256, SMEM_PROJ>>>(xh, xl, Wq, Wk, Wv, cK, cV);

    attn_kernel<<<dim3(Mq / 128, Hh, NSPLIT), 256, SMEM_ATT>>>();

    combine_kernel<<<(Mq * Nn / 4) / 256, 256>>>(out);
}